// round 4
// baseline (speedup 1.0000x reference)
#include <cuda_runtime.h>
#include <math.h>

#define Nn 50000
#define Cc 64
#define Ee 800000
#define NC (Nn*Cc)

// ---------------- device scratch (no allocations allowed) ----------------
__device__ float d_s[4][NC];        // states 2..5
__device__ float d_P[NC];           // combined GCN input per step
__device__ float d_hw[5][NC];       // GAT hw_j per step
__device__ float d_agg[4][NC];      // SAGE mean aggregates of states {x, s2, s3, s4}
__device__ float d_asrc[5][Nn];
__device__ float d_adst[5][Nn];
__device__ int   d_indeg[Nn];
__device__ int   d_rowptr[Nn+1];
__device__ int   d_fill[Nn];
__device__ int   d_csrc[Ee];
__device__ float d_dinv[Nn];        // rsqrt(indeg+1)  (GCN, self-looped degree)
__device__ float d_cntinv[Nn];      // 1/max(indeg,1)  (SAGE mean)
__device__ float d_w[14][5];        // softmax(alphas)
__device__ float d_bias[4][Cc];     // per-step combined bias
__device__ int   d_bsum[64];
__device__ int   d_boff[64];

// ---------------- zero indeg ----------------
__global__ void zero_indeg_kernel()
{
    int i = blockIdx.x*blockDim.x + threadIdx.x;
    if (i < Nn) d_indeg[i] = 0;
}

// ---------------- prep: mixture weights + combined biases ----------------
__global__ void prep_w_kernel(const float* alphas, const float* gcn_b,
                              const float* sage_b, const float* gat_b)
{
    int t = threadIdx.x;
    if (t < 14) {
        float v[5]; float m = -1e30f;
        for (int i = 0; i < 5; i++) { v[i] = alphas[t*5+i]; m = fmaxf(m, v[i]); }
        float s = 0.f;
        for (int i = 0; i < 5; i++) { v[i] = expf(v[i]-m); s += v[i]; }
        for (int i = 0; i < 5; i++) d_w[t][i] = v[i]/s;
    }
    __syncthreads();
    int step = t >> 6, c = t & 63;
    const int koff[4] = {0,2,5,9};
    float b = 0.f;
    for (int j = 0; j < step+2; j++) {
        int k = koff[step] + j;
        b += d_w[k][0]*gcn_b[k*Cc+c] + d_w[k][1]*sage_b[k*Cc+c] + d_w[k][2]*gat_b[k*Cc+c];
    }
    d_bias[step][c] = b;
}

// ---------------- CSR construction (edge_index is int32) ----
__global__ void degree_kernel(const int* ei)
{
    int e = blockIdx.x*blockDim.x + threadIdx.x;
    if (e < Ee) {
        int d = ei[Ee + e];
        if ((unsigned)d < (unsigned)Nn) atomicAdd(&d_indeg[d], 1);
    }
}

// block sums (49 blocks x 1024)
__global__ void scan1_kernel()
{
    __shared__ int sh[32];
    int b = blockIdx.x, t = threadIdx.x;
    int i = b*1024 + t;
    int v = (i < Nn) ? d_indeg[i] : 0;
    #pragma unroll
    for (int off = 16; off > 0; off >>= 1) v += __shfl_down_sync(0xffffffffu, v, off);
    if ((t & 31) == 0) sh[t >> 5] = v;
    __syncthreads();
    if (t < 32) {
        int s = sh[t];
        #pragma unroll
        for (int off = 16; off > 0; off >>= 1) s += __shfl_down_sync(0xffffffffu, s, off);
        if (t == 0) d_bsum[b] = s;
    }
}

// exclusive scan of 49 block sums (1 block, 64 threads)
__global__ void scan2_kernel(int nblocks)
{
    __shared__ int sh[64];
    int t = threadIdx.x;
    int v = (t < nblocks) ? d_bsum[t] : 0;
    sh[t] = v;
    __syncthreads();
    #pragma unroll
    for (int off = 1; off < 64; off <<= 1) {
        int xv = (t >= off) ? sh[t-off] : 0;
        __syncthreads();
        sh[t] += xv;
        __syncthreads();
    }
    if (t < nblocks) d_boff[t] = sh[t] - v;
}

// per-element scan + derived arrays (49 blocks x 1024)
__global__ void scan3_kernel()
{
    __shared__ int sh[1024];
    int b = blockIdx.x, t = threadIdx.x;
    int i = b*1024 + t;
    int v = (i < Nn) ? d_indeg[i] : 0;
    sh[t] = v;
    __syncthreads();
    #pragma unroll
    for (int off = 1; off < 1024; off <<= 1) {
        int xv = (t >= off) ? sh[t-off] : 0;
        __syncthreads();
        sh[t] += xv;
        __syncthreads();
    }
    if (i < Nn) {
        int r = d_boff[b] + sh[t] - v;
        d_rowptr[i] = r;
        d_fill[i]   = r;
        d_dinv[i]   = rsqrtf((float)(v+1));
        d_cntinv[i] = 1.0f / (float)(v > 0 ? v : 1);
        if (i == Nn-1) d_rowptr[Nn] = r + v;
    }
}

__global__ void fill_kernel(const int* ei)
{
    int e = blockIdx.x*blockDim.x + threadIdx.x;
    if (e < Ee) {
        int s = ei[e];
        int d = ei[Ee + e];
        if ((unsigned)s < (unsigned)Nn && (unsigned)d < (unsigned)Nn) {
            int pos = atomicAdd(&d_fill[d], 1);
            if ((unsigned)pos < (unsigned)Ee) d_csrc[pos] = s;
        }
    }
}

// ---------------- multi-job GEMM with packed f32x2 FMA ----------------
// D = sum_t [sc_t*W_t (+ sc2_t*W2_t)] applied to A_t:  50000x64 @ 64x64
struct GTerm { const float* A; const float* W; const float* W2; int wk; int wcol; int wk2; };
struct GJob  { float* D; int nt; GTerm t[10]; };
struct GArgs { GJob job[7]; };

#define AKSTRIDE 133   // 64-bit units per k-slice of Adup (odd -> 4-way write conflict max)

__global__ void gemm_kernel(GArgs args)
{
    extern __shared__ float sm[];
    unsigned long long* Adup = (unsigned long long*)sm;   // [64 k][AKSTRIDE] of {v,v}
    float* Ws = sm + 64*AKSTRIDE*2;                       // [64 k][64 n]
    const GJob& J = args.job[blockIdx.y];
    int tid = threadIdx.x;
    int tx = tid & 15, ty = tid >> 4;     // rows = tx + 16*m ; cols = ty*8..+7
    int row0 = blockIdx.x * 128;

    unsigned long long acc[8][4];
    #pragma unroll
    for (int m = 0; m < 8; m++)
        #pragma unroll
        for (int n2 = 0; n2 < 4; n2++) acc[m][n2] = 0ull;

    for (int tm = 0; tm < J.nt; tm++) {
        const float* A  = J.t[tm].A;
        const float* W  = J.t[tm].W;
        const float* W2 = J.t[tm].W2;
        float sc  = (J.t[tm].wk  >= 0) ? d_w[J.t[tm].wk ][J.t[tm].wcol] : 1.0f;
        float sc2 = (J.t[tm].wk2 >= 0) ? d_w[J.t[tm].wk2][J.t[tm].wcol] : 0.0f;
        __syncthreads();
        // A tile -> duplicated-pair smem, k-major
        #pragma unroll
        for (int it = 0; it < 16; it++) {
            int idx = tid + it*128;           // 0..2047
            int r = idx >> 4, k4 = (idx & 15) * 4;
            float4 v = make_float4(0.f,0.f,0.f,0.f);
            int gr = row0 + r;
            if (gr < Nn) v = *(const float4*)(A + (size_t)gr*Cc + k4);
            float vs[4] = {v.x, v.y, v.z, v.w};
            #pragma unroll
            for (int c = 0; c < 4; c++) {
                unsigned long long p = (unsigned long long)__float_as_uint(vs[c]);
                Adup[(k4+c)*AKSTRIDE + r] = p | (p << 32);
            }
        }
        // W (optionally combined pair) pre-scaled
        #pragma unroll
        for (int it = 0; it < 8; it++) {
            int idx = tid + it*128;           // 0..1023 float4s
            float4 v = *(const float4*)(W + idx*4);
            float4 o;
            o.x = sc*v.x; o.y = sc*v.y; o.z = sc*v.z; o.w = sc*v.w;
            if (W2) {
                float4 v2 = *(const float4*)(W2 + idx*4);
                o.x += sc2*v2.x; o.y += sc2*v2.y; o.z += sc2*v2.z; o.w += sc2*v2.w;
            }
            *(float4*)(Ws + idx*4) = o;
        }
        __syncthreads();
        #pragma unroll 8
        for (int k = 0; k < 64; k++) {
            unsigned long long a[8], bp[4];
            #pragma unroll
            for (int m = 0; m < 8; m++)
                a[m] = Adup[k*AKSTRIDE + tx + 16*m];
            #pragma unroll
            for (int n2 = 0; n2 < 4; n2++)
                bp[n2] = *(const unsigned long long*)(Ws + k*64 + ty*8 + n2*2);
            #pragma unroll
            for (int m = 0; m < 8; m++)
                #pragma unroll
                for (int n2 = 0; n2 < 4; n2++)
                    asm("fma.rn.f32x2 %0, %1, %2, %0;"
                        : "+l"(acc[m][n2]) : "l"(a[m]), "l"(bp[n2]));
        }
    }
    #pragma unroll
    for (int m = 0; m < 8; m++) {
        int gr = row0 + tx + 16*m;
        if (gr < Nn) {
            float o[8];
            #pragma unroll
            for (int n2 = 0; n2 < 4; n2++) {
                o[2*n2]   = __uint_as_float((unsigned)(acc[m][n2] & 0xffffffffull));
                o[2*n2+1] = __uint_as_float((unsigned)(acc[m][n2] >> 32));
            }
            float* Dp = J.D + (size_t)gr*Cc + ty*8;
            *(float4*)Dp     = make_float4(o[0],o[1],o[2],o[3]);
            *(float4*)(Dp+4) = make_float4(o[4],o[5],o[6],o[7]);
        }
    }
}

// ---------------- GAT attention scalars ----------------
__global__ void rowdot_kernel(const float* ga_src, const float* ga_dst, int ko)
{
    int j = blockIdx.y;
    int k = ko + j;
    int gw = (blockIdx.x*blockDim.x + threadIdx.x) >> 5;
    if (gw >= Nn) return;
    int lane = threadIdx.x & 31;
    float2 h  = *(const float2*)(d_hw[j] + (size_t)gw*Cc + 2*lane);
    float2 as = *(const float2*)(ga_src + k*Cc + 2*lane);
    float2 ad = *(const float2*)(ga_dst + k*Cc + 2*lane);
    float s1 = h.x*as.x + h.y*as.y;
    float s2 = h.x*ad.x + h.y*ad.y;
    #pragma unroll
    for (int off = 16; off > 0; off >>= 1) {
        s1 += __shfl_xor_sync(0xffffffffu, s1, off);
        s2 += __shfl_xor_sync(0xffffffffu, s2, off);
    }
    if (lane == 0) { d_asrc[j][gw] = s1; d_adst[j][gw] = s2; }
}

// ---------------- SAGE mean aggregate ----------------
__global__ void sage_agg_kernel(float* agg, const float* h)
{
    int gw = (blockIdx.x*blockDim.x + threadIdx.x) >> 5;
    if (gw >= Nn) return;
    int lane = threadIdx.x & 31;
    int v = gw;
    int beg = d_rowptr[v], end = d_rowptr[v+1];
    float2 acc = make_float2(0.f,0.f);
    for (int e0 = beg; e0 < end; e0 += 32) {
        int idx = e0 + lane;
        int s = 0;
        if (idx < end) s = d_csrc[idx];
        int cnt = min(32, end - e0);
        for (int t2 = 0; t2 < cnt; t2++) {
            int ss = __shfl_sync(0xffffffffu, s, t2);
            float2 p = *(const float2*)(h + (size_t)ss*Cc + 2*lane);
            acc.x += p.x; acc.y += p.y;
        }
    }
    float ci = d_cntinv[v];
    *(float2*)(agg + (size_t)v*Cc + 2*lane) = make_float2(acc.x*ci, acc.y*ci);
}

// ---------------- GCN aggregate over combined P ----------------
__global__ void gcn_agg_kernel(float* S)
{
    int gw = (blockIdx.x*blockDim.x + threadIdx.x) >> 5;
    if (gw >= Nn) return;
    int lane = threadIdx.x & 31;
    int v = gw;
    int beg = d_rowptr[v], end = d_rowptr[v+1];
    float2 acc = make_float2(0.f,0.f);
    for (int e0 = beg; e0 < end; e0 += 32) {
        int idx = e0 + lane;
        int s = 0; float cf = 0.f;
        if (idx < end) { s = d_csrc[idx]; cf = d_dinv[s]; }
        int cnt = min(32, end - e0);
        for (int t2 = 0; t2 < cnt; t2++) {
            int ss = __shfl_sync(0xffffffffu, s, t2);
            float cc = __shfl_sync(0xffffffffu, cf, t2);
            float2 p = *(const float2*)(d_P + (size_t)ss*Cc + 2*lane);
            acc.x += cc*p.x; acc.y += cc*p.y;
        }
    }
    float dv = d_dinv[v];
    float2 pv = *(const float2*)(d_P + (size_t)v*Cc + 2*lane);
    float2 sv = *(float2*)(S + (size_t)v*Cc + 2*lane);
    sv.x += dv*acc.x + dv*dv*pv.x;
    sv.y += dv*acc.y + dv*dv*pv.y;
    *(float2*)(S + (size_t)v*Cc + 2*lane) = sv;
}

// ---------------- identity branch + combined bias ----------------
struct PWArgs { const float* st[5]; };
__global__ void pointwise_kernel(float* S, PWArgs a, int ko, int nj, int step)
{
    int idx = blockIdx.x*blockDim.x + threadIdx.x;
    if (idx >= NC) return;
    int c = idx & 63;
    float v = d_bias[step][c];
    for (int j = 0; j < nj; j++)
        v += d_w[ko+j][3] * a.st[j][idx];
    S[idx] += v;
}

// ---------------- GAT: segment softmax + weighted gather ----------------
__global__ void gat_agg_kernel(float* S, int ko, int nj)
{
    int gw = (blockIdx.x*blockDim.x + threadIdx.x) >> 5;
    if (gw >= Nn) return;
    int lane = threadIdx.x & 31;
    int v = gw;
    int beg = d_rowptr[v], end = d_rowptr[v+1];
    float2 tot = make_float2(0.f,0.f);
    for (int j = 0; j < nj; j++) {
        const float* hw = d_hw[j];
        const float* as = d_asrc[j];
        float adv = d_adst[j][v];
        float e0s = as[v] + adv;
        float eself = e0s > 0.f ? e0s : 0.2f*e0s;
        float m = eself;
        for (int e0 = beg; e0 < end; e0 += 32) {
            int idx = e0 + lane;
            float e = -1e30f;
            if (idx < end) {
                float tv = as[d_csrc[idx]] + adv;
                e = tv > 0.f ? tv : 0.2f*tv;
            }
            m = fmaxf(m, e);
        }
        #pragma unroll
        for (int off = 16; off > 0; off >>= 1)
            m = fmaxf(m, __shfl_xor_sync(0xffffffffu, m, off));
        float denom = 0.f;
        float2 acc = make_float2(0.f,0.f);
        {
            float p = __expf(eself - m);
            if (lane == 0) denom = p;
            float2 hv = *(const float2*)(hw + (size_t)v*Cc + 2*lane);
            acc.x += p*hv.x; acc.y += p*hv.y;
        }
        for (int e0 = beg; e0 < end; e0 += 32) {
            int idx = e0 + lane;
            int s = 0; float p = 0.f;
            if (idx < end) {
                s = d_csrc[idx];
                float tv = as[s] + adv;
                tv = tv > 0.f ? tv : 0.2f*tv;
                p = __expf(tv - m);
            }
            denom += p;
            int cnt = min(32, end - e0);
            for (int t2 = 0; t2 < cnt; t2++) {
                float pp = __shfl_sync(0xffffffffu, p, t2);
                int ss = __shfl_sync(0xffffffffu, s, t2);
                float2 hsv = *(const float2*)(hw + (size_t)ss*Cc + 2*lane);
                acc.x += pp*hsv.x; acc.y += pp*hsv.y;
            }
        }
        #pragma unroll
        for (int off = 16; off > 0; off >>= 1)
            denom += __shfl_xor_sync(0xffffffffu, denom, off);
        float wcoef = d_w[ko+j][2] / denom;
        tot.x += wcoef*acc.x; tot.y += wcoef*acc.y;
    }
    float2 sv = *(float2*)(S + (size_t)v*Cc + 2*lane);
    sv.x += tot.x; sv.y += tot.y;
    *(float2*)(S + (size_t)v*Cc + 2*lane) = sv;
}

// ---------------- output ----------------
__global__ void final_kernel(float* out)
{
    int idx = blockIdx.x*blockDim.x + threadIdx.x;
    if (idx >= NC) return;
    out[idx] = 0.25f*(d_s[0][idx] + d_s[1][idx] + d_s[2][idx] + d_s[3][idx]);
}

// ---------------- host orchestration ----------------
extern "C" void kernel_launch(void* const* d_in, const int* in_sizes, int n_in,
                              void* d_out, int out_size)
{
    const float* x       = (const float*)d_in[0];
    const int*   ei      = (const int*)d_in[1];     // int32
    const float* alphas  = (const float*)d_in[2];
    const float* gcn_W   = (const float*)d_in[3];
    const float* gcn_b   = (const float*)d_in[4];
    const float* sage_Wl = (const float*)d_in[5];
    const float* sage_Wr = (const float*)d_in[6];
    const float* sage_b  = (const float*)d_in[7];
    const float* gat_W   = (const float*)d_in[8];
    const float* ga_src  = (const float*)d_in[9];
    const float* ga_dst  = (const float*)d_in[10];
    const float* gat_b   = (const float*)d_in[11];
    float* out = (float*)d_out;
    (void)in_sizes; (void)n_in; (void)out_size;

    float *sbase, *Pp, *hwbase, *aggbase;
    cudaGetSymbolAddress((void**)&sbase,   d_s);
    cudaGetSymbolAddress((void**)&Pp,      d_P);
    cudaGetSymbolAddress((void**)&hwbase,  d_hw);
    cudaGetSymbolAddress((void**)&aggbase, d_agg);

    const int SMEMSZ = (64*AKSTRIDE*2 + 64*64) * 4;   // 84480 B
    cudaFuncSetAttribute(gemm_kernel, cudaFuncAttributeMaxDynamicSharedMemorySize, SMEMSZ);

    const int NBLK = (Nn + 1023)/1024;   // 49

    // ---- prep ----
    zero_indeg_kernel<<<(Nn+511)/512,512>>>();
    prep_w_kernel<<<1,256>>>(alphas, gcn_b, sage_b, gat_b);
    degree_kernel<<<(Ee+255)/256,256>>>(ei);
    scan1_kernel<<<NBLK,1024>>>();
    scan2_kernel<<<1,64>>>(NBLK);
    scan3_kernel<<<NBLK,1024>>>();
    fill_kernel<<<(Ee+255)/256,256>>>(ei);
    sage_agg_kernel<<<6250,256>>>(aggbase, x);          // mean-agg of x

    const int koff[4] = {0,2,5,9};
    for (int step = 0; step < 4; step++) {
        int nj = step + 2;
        int ko = koff[step];
        if (step >= 1)
            sage_agg_kernel<<<6250,256>>>(aggbase + (size_t)step*NC,
                                          sbase + (size_t)(step-1)*NC);

        GArgs ga;
        // job0: combined GCN input P  (j=0,1 share A=x -> weight-merged)
        {
            GJob& jb = ga.job[0];
            jb.D = Pp;
            int n = 0;
            jb.t[n++] = GTerm{ x, gcn_W + (size_t)ko*4096, gcn_W + (size_t)(ko+1)*4096,
                               ko, 0, ko+1 };
            for (int j = 2; j < nj; j++)
                jb.t[n++] = GTerm{ sbase + (size_t)(j-2)*NC, gcn_W + (size_t)(ko+j)*4096,
                                   nullptr, ko+j, 0, -1 };
            jb.nt = n;
        }
        // job1: SAGE sum -> new state S (first writer)
        {
            GJob& jb = ga.job[1];
            jb.D = sbase + (size_t)step*NC;
            int n = 0;
            // j=0,1 share agg_x and x -> weight-merged
            jb.t[n++] = GTerm{ aggbase, sage_Wl + (size_t)ko*4096,
                               sage_Wl + (size_t)(ko+1)*4096, ko, 1, ko+1 };
            jb.t[n++] = GTerm{ x, sage_Wr + (size_t)ko*4096,
                               sage_Wr + (size_t)(ko+1)*4096, ko, 1, ko+1 };
            for (int j = 2; j < nj; j++) {
                jb.t[n++] = GTerm{ aggbase + (size_t)(j-1)*NC,
                                   sage_Wl + (size_t)(ko+j)*4096, nullptr, ko+j, 1, -1 };
                jb.t[n++] = GTerm{ sbase + (size_t)(j-2)*NC,
                                   sage_Wr + (size_t)(ko+j)*4096, nullptr, ko+j, 1, -1 };
            }
            jb.nt = n;
        }
        // jobs 2..: GAT hw_j (unscaled; nonlinear downstream)
        for (int j = 0; j < nj; j++) {
            const float* st = (j <= 1) ? x : sbase + (size_t)(j-2)*NC;
            ga.job[2+j].D = hwbase + (size_t)j*NC; ga.job[2+j].nt = 1;
            ga.job[2+j].t[0] = GTerm{ st, gat_W + (size_t)(ko+j)*4096, nullptr, -1, 0, -1 };
        }
        gemm_kernel<<<dim3(391, 2+nj), 128, SMEMSZ>>>(ga);

        rowdot_kernel<<<dim3(6250, nj), 256>>>(ga_src, ga_dst, ko);
        gcn_agg_kernel<<<6250,256>>>(sbase + (size_t)step*NC);

        PWArgs pw;
        for (int j = 0; j < nj; j++)
            pw.st[j] = (j <= 1) ? x : sbase + (size_t)(j-2)*NC;
        pointwise_kernel<<<6250,512>>>(sbase + (size_t)step*NC, pw, ko, nj, step);

        gat_agg_kernel<<<6250,256>>>(sbase + (size_t)step*NC, ko, nj);
    }
    final_kernel<<<6250,512>>>(out);
}

// round 5
// speedup vs baseline: 1.5225x; 1.5225x over previous
#include <cuda_runtime.h>
#include <math.h>

#define Nn 50000
#define Cc 64
#define Ee 800000
#define NC (Nn*Cc)

// ---------------- device scratch (no allocations allowed) ----------------
__device__ float d_s[4][NC];        // states 2..5
__device__ float d_P[NC];           // combined GCN input per step
__device__ float d_hw[5][NC];       // GAT hw_j per step
__device__ float d_agg[4][NC];      // SAGE mean aggregates of states {x, s2, s3, s4}
__device__ float d_asrc[5][Nn];
__device__ float d_adst[5][Nn];
__device__ int   d_indeg[Nn];
__device__ int   d_rowptr[Nn+1];
__device__ int   d_fill[Nn];
__device__ int   d_csrc[Ee];
__device__ float d_dinv[Nn];        // rsqrt(indeg+1)  (GCN, self-looped degree)
__device__ float d_cntinv[Nn];      // 1/max(indeg,1)  (SAGE mean)
__device__ float d_w[14][5];        // softmax(alphas)
__device__ float d_bias[4][Cc];     // per-step combined bias
__device__ int   d_bsum[64];
__device__ int   d_boff[64];

// ---------------- zero indeg ----------------
__global__ void zero_indeg_kernel()
{
    int i = blockIdx.x*blockDim.x + threadIdx.x;
    if (i < Nn) d_indeg[i] = 0;
}

// ---------------- prep: mixture weights + combined biases ----------------
__global__ void prep_w_kernel(const float* alphas, const float* gcn_b,
                              const float* sage_b, const float* gat_b)
{
    int t = threadIdx.x;
    if (t < 14) {
        float v[5]; float m = -1e30f;
        for (int i = 0; i < 5; i++) { v[i] = alphas[t*5+i]; m = fmaxf(m, v[i]); }
        float s = 0.f;
        for (int i = 0; i < 5; i++) { v[i] = expf(v[i]-m); s += v[i]; }
        for (int i = 0; i < 5; i++) d_w[t][i] = v[i]/s;
    }
    __syncthreads();
    int step = t >> 6, c = t & 63;
    const int koff[4] = {0,2,5,9};
    float b = 0.f;
    for (int j = 0; j < step+2; j++) {
        int k = koff[step] + j;
        b += d_w[k][0]*gcn_b[k*Cc+c] + d_w[k][1]*sage_b[k*Cc+c] + d_w[k][2]*gat_b[k*Cc+c];
    }
    d_bias[step][c] = b;
}

// ---------------- CSR construction (edge_index is int32) ----
__global__ void degree_kernel(const int* ei)
{
    int e = blockIdx.x*blockDim.x + threadIdx.x;
    if (e < Ee) {
        int d = ei[Ee + e];
        if ((unsigned)d < (unsigned)Nn) atomicAdd(&d_indeg[d], 1);
    }
}

// block sums (49 blocks x 1024)
__global__ void scan1_kernel()
{
    __shared__ int sh[32];
    int b = blockIdx.x, t = threadIdx.x;
    int i = b*1024 + t;
    int v = (i < Nn) ? d_indeg[i] : 0;
    #pragma unroll
    for (int off = 16; off > 0; off >>= 1) v += __shfl_down_sync(0xffffffffu, v, off);
    if ((t & 31) == 0) sh[t >> 5] = v;
    __syncthreads();
    if (t < 32) {
        int s = sh[t];
        #pragma unroll
        for (int off = 16; off > 0; off >>= 1) s += __shfl_down_sync(0xffffffffu, s, off);
        if (t == 0) d_bsum[b] = s;
    }
}

// exclusive scan of block sums (1 block, 64 threads)
__global__ void scan2_kernel(int nblocks)
{
    __shared__ int sh[64];
    int t = threadIdx.x;
    int v = (t < nblocks) ? d_bsum[t] : 0;
    sh[t] = v;
    __syncthreads();
    #pragma unroll
    for (int off = 1; off < 64; off <<= 1) {
        int xv = (t >= off) ? sh[t-off] : 0;
        __syncthreads();
        sh[t] += xv;
        __syncthreads();
    }
    if (t < nblocks) d_boff[t] = sh[t] - v;
}

// per-element scan + derived arrays (49 blocks x 1024)
__global__ void scan3_kernel()
{
    __shared__ int sh[1024];
    int b = blockIdx.x, t = threadIdx.x;
    int i = b*1024 + t;
    int v = (i < Nn) ? d_indeg[i] : 0;
    sh[t] = v;
    __syncthreads();
    #pragma unroll
    for (int off = 1; off < 1024; off <<= 1) {
        int xv = (t >= off) ? sh[t-off] : 0;
        __syncthreads();
        sh[t] += xv;
        __syncthreads();
    }
    if (i < Nn) {
        int r = d_boff[b] + sh[t] - v;
        d_rowptr[i] = r;
        d_fill[i]   = r;
        d_dinv[i]   = rsqrtf((float)(v+1));
        d_cntinv[i] = 1.0f / (float)(v > 0 ? v : 1);
        if (i == Nn-1) d_rowptr[Nn] = r + v;
    }
}

__global__ void fill_kernel(const int* ei)
{
    int e = blockIdx.x*blockDim.x + threadIdx.x;
    if (e < Ee) {
        int s = ei[e];
        int d = ei[Ee + e];
        if ((unsigned)s < (unsigned)Nn && (unsigned)d < (unsigned)Nn) {
            int pos = atomicAdd(&d_fill[d], 1);
            if ((unsigned)pos < (unsigned)Ee) d_csrc[pos] = s;
        }
    }
}

// ---------------- multi-job GEMM (scalar FFMA, R3-style) ----------------
// D = sum_t [sc_t*W_t (+ sc2_t*W2_t)] applied to A_t:  50000x64 @ 64x64
struct GTerm { const float* A; const float* W; const float* W2; int wk; int wcol; int wk2; };
struct GJob  { float* D; int nt; GTerm t[10]; };
struct GArgs { GJob job[7]; };

__global__ void gemm_kernel(GArgs args)
{
    extern __shared__ float sm[];
    float* Ast = sm;             // [64 k][132 r]  A transposed, padded
    float* Ws  = sm + 64*132;    // [64 k][64 n]
    const GJob& J = args.job[blockIdx.y];
    int tid = threadIdx.x;
    int tx = tid & 15, ty = tid >> 4;     // 16 row-groups x 8 col-groups
    int row0 = blockIdx.x * 128;
    float acc[8][8];
    #pragma unroll
    for (int m = 0; m < 8; m++)
        #pragma unroll
        for (int n = 0; n < 8; n++) acc[m][n] = 0.f;

    for (int tm = 0; tm < J.nt; tm++) {
        const float* A  = J.t[tm].A;
        const float* W  = J.t[tm].W;
        const float* W2 = J.t[tm].W2;
        float sc  = (J.t[tm].wk  >= 0) ? d_w[J.t[tm].wk ][J.t[tm].wcol] : 1.0f;
        float sc2 = (J.t[tm].wk2 >= 0) ? d_w[J.t[tm].wk2][J.t[tm].wcol] : 0.0f;
        __syncthreads();
        // load A tile transposed into smem
        #pragma unroll
        for (int it = 0; it < 16; it++) {
            int idx = tid + it*128;           // 0..2047
            int r = idx >> 4, k4 = (idx & 15) * 4;
            float4 v = make_float4(0.f,0.f,0.f,0.f);
            int gr = row0 + r;
            if (gr < Nn) v = *(const float4*)(A + (size_t)gr*Cc + k4);
            Ast[(k4+0)*132 + r] = v.x;
            Ast[(k4+1)*132 + r] = v.y;
            Ast[(k4+2)*132 + r] = v.z;
            Ast[(k4+3)*132 + r] = v.w;
        }
        // load W (optionally merged pair) pre-scaled
        #pragma unroll
        for (int it = 0; it < 8; it++) {
            int idx = tid + it*128;           // 0..1023 float4s
            float4 v = *(const float4*)(W + idx*4);
            float4 o;
            o.x = sc*v.x; o.y = sc*v.y; o.z = sc*v.z; o.w = sc*v.w;
            if (W2) {
                float4 v2 = *(const float4*)(W2 + idx*4);
                o.x += sc2*v2.x; o.y += sc2*v2.y; o.z += sc2*v2.z; o.w += sc2*v2.w;
            }
            *(float4*)(Ws + idx*4) = o;
        }
        __syncthreads();
        #pragma unroll 8
        for (int k = 0; k < 64; k++) {
            float4 a0 = *(const float4*)(Ast + k*132 + tx*8);
            float4 a1 = *(const float4*)(Ast + k*132 + tx*8 + 4);
            float4 b0 = *(const float4*)(Ws + k*64 + ty*8);
            float4 b1 = *(const float4*)(Ws + k*64 + ty*8 + 4);
            float a[8] = {a0.x,a0.y,a0.z,a0.w,a1.x,a1.y,a1.z,a1.w};
            float b[8] = {b0.x,b0.y,b0.z,b0.w,b1.x,b1.y,b1.z,b1.w};
            #pragma unroll
            for (int m = 0; m < 8; m++)
                #pragma unroll
                for (int n = 0; n < 8; n++)
                    acc[m][n] += a[m]*b[n];
        }
    }
    #pragma unroll
    for (int m = 0; m < 8; m++) {
        int gr = row0 + tx*8 + m;
        if (gr < Nn) {
            float* Dp = J.D + (size_t)gr*Cc + ty*8;
            *(float4*)Dp     = make_float4(acc[m][0],acc[m][1],acc[m][2],acc[m][3]);
            *(float4*)(Dp+4) = make_float4(acc[m][4],acc[m][5],acc[m][6],acc[m][7]);
        }
    }
}

// ---------------- GAT attention scalars ----------------
__global__ void rowdot_kernel(const float* ga_src, const float* ga_dst, int ko)
{
    int j = blockIdx.y;
    int k = ko + j;
    int gw = (blockIdx.x*blockDim.x + threadIdx.x) >> 5;
    if (gw >= Nn) return;
    int lane = threadIdx.x & 31;
    float2 h  = *(const float2*)(d_hw[j] + (size_t)gw*Cc + 2*lane);
    float2 as = *(const float2*)(ga_src + k*Cc + 2*lane);
    float2 ad = *(const float2*)(ga_dst + k*Cc + 2*lane);
    float s1 = h.x*as.x + h.y*as.y;
    float s2 = h.x*ad.x + h.y*ad.y;
    #pragma unroll
    for (int off = 16; off > 0; off >>= 1) {
        s1 += __shfl_xor_sync(0xffffffffu, s1, off);
        s2 += __shfl_xor_sync(0xffffffffu, s2, off);
    }
    if (lane == 0) { d_asrc[j][gw] = s1; d_adst[j][gw] = s2; }
}

// ---------------- SAGE mean aggregate ----------------
__global__ void sage_agg_kernel(float* agg, const float* h)
{
    int gw = (blockIdx.x*blockDim.x + threadIdx.x) >> 5;
    if (gw >= Nn) return;
    int lane = threadIdx.x & 31;
    int v = gw;
    int beg = d_rowptr[v], end = d_rowptr[v+1];
    float2 acc = make_float2(0.f,0.f);
    for (int e0 = beg; e0 < end; e0 += 32) {
        int idx = e0 + lane;
        int s = 0;
        if (idx < end) s = d_csrc[idx];
        int cnt = min(32, end - e0);
        for (int t2 = 0; t2 < cnt; t2++) {
            int ss = __shfl_sync(0xffffffffu, s, t2);
            float2 p = *(const float2*)(h + (size_t)ss*Cc + 2*lane);
            acc.x += p.x; acc.y += p.y;
        }
    }
    float ci = d_cntinv[v];
    *(float2*)(agg + (size_t)v*Cc + 2*lane) = make_float2(acc.x*ci, acc.y*ci);
}

// ---------------- GCN aggregate over combined P ----------------
__global__ void gcn_agg_kernel(float* S)
{
    int gw = (blockIdx.x*blockDim.x + threadIdx.x) >> 5;
    if (gw >= Nn) return;
    int lane = threadIdx.x & 31;
    int v = gw;
    int beg = d_rowptr[v], end = d_rowptr[v+1];
    float2 acc = make_float2(0.f,0.f);
    for (int e0 = beg; e0 < end; e0 += 32) {
        int idx = e0 + lane;
        int s = 0; float cf = 0.f;
        if (idx < end) { s = d_csrc[idx]; cf = d_dinv[s]; }
        int cnt = min(32, end - e0);
        for (int t2 = 0; t2 < cnt; t2++) {
            int ss = __shfl_sync(0xffffffffu, s, t2);
            float cc = __shfl_sync(0xffffffffu, cf, t2);
            float2 p = *(const float2*)(d_P + (size_t)ss*Cc + 2*lane);
            acc.x += cc*p.x; acc.y += cc*p.y;
        }
    }
    float dv = d_dinv[v];
    float2 pv = *(const float2*)(d_P + (size_t)v*Cc + 2*lane);
    float2 sv = *(float2*)(S + (size_t)v*Cc + 2*lane);
    sv.x += dv*acc.x + dv*dv*pv.x;
    sv.y += dv*acc.y + dv*dv*pv.y;
    *(float2*)(S + (size_t)v*Cc + 2*lane) = sv;
}

// ---------------- identity branch + combined bias ----------------
struct PWArgs { const float* st[5]; };
__global__ void pointwise_kernel(float* S, PWArgs a, int ko, int nj, int step)
{
    int idx = blockIdx.x*blockDim.x + threadIdx.x;
    if (idx >= NC) return;
    int c = idx & 63;
    float v = d_bias[step][c];
    for (int j = 0; j < nj; j++)
        v += d_w[ko+j][3] * a.st[j][idx];
    S[idx] += v;
}

// ---------------- GAT: segment softmax + weighted gather ----------------
__global__ void gat_agg_kernel(float* S, int ko, int nj)
{
    int gw = (blockIdx.x*blockDim.x + threadIdx.x) >> 5;
    if (gw >= Nn) return;
    int lane = threadIdx.x & 31;
    int v = gw;
    int beg = d_rowptr[v], end = d_rowptr[v+1];
    float2 tot = make_float2(0.f,0.f);
    for (int j = 0; j < nj; j++) {
        const float* hw = d_hw[j];
        const float* as = d_asrc[j];
        float adv = d_adst[j][v];
        float e0s = as[v] + adv;
        float eself = e0s > 0.f ? e0s : 0.2f*e0s;
        float m = eself;
        for (int e0 = beg; e0 < end; e0 += 32) {
            int idx = e0 + lane;
            float e = -1e30f;
            if (idx < end) {
                float tv = as[d_csrc[idx]] + adv;
                e = tv > 0.f ? tv : 0.2f*tv;
            }
            m = fmaxf(m, e);
        }
        #pragma unroll
        for (int off = 16; off > 0; off >>= 1)
            m = fmaxf(m, __shfl_xor_sync(0xffffffffu, m, off));
        float denom = 0.f;
        float2 acc = make_float2(0.f,0.f);
        {
            float p = __expf(eself - m);
            if (lane == 0) denom = p;
            float2 hv = *(const float2*)(hw + (size_t)v*Cc + 2*lane);
            acc.x += p*hv.x; acc.y += p*hv.y;
        }
        for (int e0 = beg; e0 < end; e0 += 32) {
            int idx = e0 + lane;
            int s = 0; float p = 0.f;
            if (idx < end) {
                s = d_csrc[idx];
                float tv = as[s] + adv;
                tv = tv > 0.f ? tv : 0.2f*tv;
                p = __expf(tv - m);
            }
            denom += p;
            int cnt = min(32, end - e0);
            for (int t2 = 0; t2 < cnt; t2++) {
                float pp = __shfl_sync(0xffffffffu, p, t2);
                int ss = __shfl_sync(0xffffffffu, s, t2);
                float2 hsv = *(const float2*)(hw + (size_t)ss*Cc + 2*lane);
                acc.x += pp*hsv.x; acc.y += pp*hsv.y;
            }
        }
        #pragma unroll
        for (int off = 16; off > 0; off >>= 1)
            denom += __shfl_xor_sync(0xffffffffu, denom, off);
        float wcoef = d_w[ko+j][2] / denom;
        tot.x += wcoef*acc.x; tot.y += wcoef*acc.y;
    }
    float2 sv = *(float2*)(S + (size_t)v*Cc + 2*lane);
    sv.x += tot.x; sv.y += tot.y;
    *(float2*)(S + (size_t)v*Cc + 2*lane) = sv;
}

// ---------------- output ----------------
__global__ void final_kernel(float* out)
{
    int idx = blockIdx.x*blockDim.x + threadIdx.x;
    if (idx >= NC) return;
    out[idx] = 0.25f*(d_s[0][idx] + d_s[1][idx] + d_s[2][idx] + d_s[3][idx]);
}

// ---------------- host orchestration ----------------
extern "C" void kernel_launch(void* const* d_in, const int* in_sizes, int n_in,
                              void* d_out, int out_size)
{
    const float* x       = (const float*)d_in[0];
    const int*   ei      = (const int*)d_in[1];     // int32
    const float* alphas  = (const float*)d_in[2];
    const float* gcn_W   = (const float*)d_in[3];
    const float* gcn_b   = (const float*)d_in[4];
    const float* sage_Wl = (const float*)d_in[5];
    const float* sage_Wr = (const float*)d_in[6];
    const float* sage_b  = (const float*)d_in[7];
    const float* gat_W   = (const float*)d_in[8];
    const float* ga_src  = (const float*)d_in[9];
    const float* ga_dst  = (const float*)d_in[10];
    const float* gat_b   = (const float*)d_in[11];
    float* out = (float*)d_out;
    (void)in_sizes; (void)n_in; (void)out_size;

    float *sbase, *Pp, *hwbase, *aggbase;
    cudaGetSymbolAddress((void**)&sbase,   d_s);
    cudaGetSymbolAddress((void**)&Pp,      d_P);
    cudaGetSymbolAddress((void**)&hwbase,  d_hw);
    cudaGetSymbolAddress((void**)&aggbase, d_agg);

    const int SMEMSZ = (64*132 + 64*64) * 4;   // 50176 B
    cudaFuncSetAttribute(gemm_kernel, cudaFuncAttributeMaxDynamicSharedMemorySize, SMEMSZ);

    const int NBLK = (Nn + 1023)/1024;   // 49

    // ---- prep ----
    zero_indeg_kernel<<<(Nn+511)/512,512>>>();
    prep_w_kernel<<<1,256>>>(alphas, gcn_b, sage_b, gat_b);
    degree_kernel<<<(Ee+255)/256,256>>>(ei);
    scan1_kernel<<<NBLK,1024>>>();
    scan2_kernel<<<1,64>>>(NBLK);
    scan3_kernel<<<NBLK,1024>>>();
    fill_kernel<<<(Ee+255)/256,256>>>(ei);
    sage_agg_kernel<<<6250,256>>>(aggbase, x);          // mean-agg of x

    const int koff[4] = {0,2,5,9};
    for (int step = 0; step < 4; step++) {
        int nj = step + 2;
        int ko = koff[step];
        if (step >= 1)
            sage_agg_kernel<<<6250,256>>>(aggbase + (size_t)step*NC,
                                          sbase + (size_t)(step-1)*NC);

        GArgs ga;
        // job0: combined GCN input P  (j=0,1 share A=x -> weight-merged)
        {
            GJob& jb = ga.job[0];
            jb.D = Pp;
            int n = 0;
            jb.t[n++] = GTerm{ x, gcn_W + (size_t)ko*4096, gcn_W + (size_t)(ko+1)*4096,
                               ko, 0, ko+1 };
            for (int j = 2; j < nj; j++)
                jb.t[n++] = GTerm{ sbase + (size_t)(j-2)*NC, gcn_W + (size_t)(ko+j)*4096,
                                   nullptr, ko+j, 0, -1 };
            jb.nt = n;
        }
        // job1: SAGE sum -> new state S (first writer)
        {
            GJob& jb = ga.job[1];
            jb.D = sbase + (size_t)step*NC;
            int n = 0;
            jb.t[n++] = GTerm{ aggbase, sage_Wl + (size_t)ko*4096,
                               sage_Wl + (size_t)(ko+1)*4096, ko, 1, ko+1 };
            jb.t[n++] = GTerm{ x, sage_Wr + (size_t)ko*4096,
                               sage_Wr + (size_t)(ko+1)*4096, ko, 1, ko+1 };
            for (int j = 2; j < nj; j++) {
                jb.t[n++] = GTerm{ aggbase + (size_t)(j-1)*NC,
                                   sage_Wl + (size_t)(ko+j)*4096, nullptr, ko+j, 1, -1 };
                jb.t[n++] = GTerm{ sbase + (size_t)(j-2)*NC,
                                   sage_Wr + (size_t)(ko+j)*4096, nullptr, ko+j, 1, -1 };
            }
            jb.nt = n;
        }
        // jobs 2..: GAT hw_j (unscaled; nonlinear downstream)
        for (int j = 0; j < nj; j++) {
            const float* st = (j <= 1) ? x : sbase + (size_t)(j-2)*NC;
            ga.job[2+j].D = hwbase + (size_t)j*NC; ga.job[2+j].nt = 1;
            ga.job[2+j].t[0] = GTerm{ st, gat_W + (size_t)(ko+j)*4096, nullptr, -1, 0, -1 };
        }
        gemm_kernel<<<dim3(391, 2+nj), 128, SMEMSZ>>>(ga);

        rowdot_kernel<<<dim3(6250, nj), 256>>>(ga_src, ga_dst, ko);
        gcn_agg_kernel<<<6250,256>>>(sbase + (size_t)step*NC);

        PWArgs pw;
        for (int j = 0; j < nj; j++)
            pw.st[j] = (j <= 1) ? x : sbase + (size_t)(j-2)*NC;
        pointwise_kernel<<<6250,512>>>(sbase + (size_t)step*NC, pw, ko, nj, step);

        gat_agg_kernel<<<6250,256>>>(sbase + (size_t)step*NC, ko, nj);
    }
    final_kernel<<<6250,512>>>(out);
}

// round 7
// speedup vs baseline: 1.6962x; 1.1141x over previous
#include <cuda_runtime.h>
#include <math.h>

#define Nn 50000
#define Cc 64
#define Ee 800000
#define NC (Nn*Cc)

// ---------------- device scratch ----------------
__device__ float d_s[4][NC];        // states 2..5
__device__ float d_P[NC];           // combined GCN input per step
__device__ float d_hw[5][NC];       // GAT hw_j per step
__device__ float d_agg[4][NC];      // SAGE mean aggregates
__device__ float d_asrc[5][Nn];
__device__ float d_adst[5][Nn];
__device__ int   d_indeg[Nn];
__device__ int   d_rowptr[Nn+1];
__device__ int   d_fill[Nn];
__device__ int   d_csrc[Ee];
__device__ float d_dinv[Nn];
__device__ float d_cntinv[Nn];
__device__ float d_w[14][5];
__device__ float d_bias[4][Cc];
__device__ int   d_bsum[64];
__device__ int   d_boff[64];

__global__ void zero_indeg_kernel()
{
    int i = blockIdx.x*blockDim.x + threadIdx.x;
    if (i < Nn) d_indeg[i] = 0;
}

__global__ void prep_w_kernel(const float* alphas, const float* gcn_b,
                              const float* sage_b, const float* gat_b)
{
    int t = threadIdx.x;
    if (t < 14) {
        float v[5]; float m = -1e30f;
        for (int i = 0; i < 5; i++) { v[i] = alphas[t*5+i]; m = fmaxf(m, v[i]); }
        float s = 0.f;
        for (int i = 0; i < 5; i++) { v[i] = expf(v[i]-m); s += v[i]; }
        for (int i = 0; i < 5; i++) d_w[t][i] = v[i]/s;
    }
    __syncthreads();
    int step = t >> 6, c = t & 63;
    const int koff[4] = {0,2,5,9};
    float b = 0.f;
    for (int j = 0; j < step+2; j++) {
        int k = koff[step] + j;
        b += d_w[k][0]*gcn_b[k*Cc+c] + d_w[k][1]*sage_b[k*Cc+c] + d_w[k][2]*gat_b[k*Cc+c];
    }
    d_bias[step][c] = b;
}

// ---------------- CSR construction (edge_index is int32) ----
__global__ void degree_kernel(const int* ei)
{
    int e = blockIdx.x*blockDim.x + threadIdx.x;
    if (e < Ee) {
        int d = ei[Ee + e];
        if ((unsigned)d < (unsigned)Nn) atomicAdd(&d_indeg[d], 1);
    }
}

__global__ void scan1_kernel()
{
    __shared__ int sh[32];
    int b = blockIdx.x, t = threadIdx.x;
    int i = b*1024 + t;
    int v = (i < Nn) ? d_indeg[i] : 0;
    #pragma unroll
    for (int off = 16; off > 0; off >>= 1) v += __shfl_down_sync(0xffffffffu, v, off);
    if ((t & 31) == 0) sh[t >> 5] = v;
    __syncthreads();
    if (t < 32) {
        int s = sh[t];
        #pragma unroll
        for (int off = 16; off > 0; off >>= 1) s += __shfl_down_sync(0xffffffffu, s, off);
        if (t == 0) d_bsum[b] = s;
    }
}

__global__ void scan2_kernel(int nblocks)
{
    __shared__ int sh[64];
    int t = threadIdx.x;
    int v = (t < nblocks) ? d_bsum[t] : 0;
    sh[t] = v;
    __syncthreads();
    #pragma unroll
    for (int off = 1; off < 64; off <<= 1) {
        int xv = (t >= off) ? sh[t-off] : 0;
        __syncthreads();
        sh[t] += xv;
        __syncthreads();
    }
    if (t < nblocks) d_boff[t] = sh[t] - v;
}

__global__ void scan3_kernel()
{
    __shared__ int sh[1024];
    int b = blockIdx.x, t = threadIdx.x;
    int i = b*1024 + t;
    int v = (i < Nn) ? d_indeg[i] : 0;
    sh[t] = v;
    __syncthreads();
    #pragma unroll
    for (int off = 1; off < 1024; off <<= 1) {
        int xv = (t >= off) ? sh[t-off] : 0;
        __syncthreads();
        sh[t] += xv;
        __syncthreads();
    }
    if (i < Nn) {
        int r = d_boff[b] + sh[t] - v;
        d_rowptr[i] = r;
        d_fill[i]   = r;
        d_dinv[i]   = rsqrtf((float)(v+1));
        d_cntinv[i] = 1.0f / (float)(v > 0 ? v : 1);
        if (i == Nn-1) d_rowptr[Nn] = r + v;
    }
}

__global__ void fill_kernel(const int* ei)
{
    int e = blockIdx.x*blockDim.x + threadIdx.x;
    if (e < Ee) {
        int s = ei[e];
        int d = ei[Ee + e];
        if ((unsigned)s < (unsigned)Nn && (unsigned)d < (unsigned)Nn) {
            int pos = atomicAdd(&d_fill[d], 1);
            if ((unsigned)pos < (unsigned)Ee) d_csrc[pos] = s;
        }
    }
}

// ---------------- multi-job GEMM (scalar FFMA) + diag/bias folding ----------------
struct GTerm { const float* A; const float* W; const float* W2; int wk; int wcol; int wk2; int addDiag; };
struct GJob  { float* D; int nt; int biasStep; GTerm t[10]; };
struct GArgs { GJob job[7]; };

__global__ void gemm_kernel(GArgs args)
{
    extern __shared__ float sm[];
    float* Ast = sm;             // [64 k][132 r]
    float* Ws  = sm + 64*132;    // [64 k][64 n]
    const GJob& J = args.job[blockIdx.y];
    int tid = threadIdx.x;
    int tx = tid & 15, ty = tid >> 4;
    int row0 = blockIdx.x * 128;
    float acc[8][8];
    #pragma unroll
    for (int m = 0; m < 8; m++)
        #pragma unroll
        for (int n = 0; n < 8; n++) acc[m][n] = 0.f;

    for (int tm = 0; tm < J.nt; tm++) {
        const float* A  = J.t[tm].A;
        const float* W  = J.t[tm].W;
        const float* W2 = J.t[tm].W2;
        float sc  = (J.t[tm].wk  >= 0) ? d_w[J.t[tm].wk ][J.t[tm].wcol] : 1.0f;
        float sc2 = (J.t[tm].wk2 >= 0) ? d_w[J.t[tm].wk2][J.t[tm].wcol] : 0.0f;
        float dg = 0.f;
        if (J.t[tm].addDiag) {
            dg = d_w[J.t[tm].wk][3];
            if (J.t[tm].wk2 >= 0) dg += d_w[J.t[tm].wk2][3];
        }
        __syncthreads();
        #pragma unroll
        for (int it = 0; it < 16; it++) {
            int idx = tid + it*128;
            int r = idx >> 4, k4 = (idx & 15) * 4;
            float4 v = make_float4(0.f,0.f,0.f,0.f);
            int gr = row0 + r;
            if (gr < Nn) v = *(const float4*)(A + (size_t)gr*Cc + k4);
            Ast[(k4+0)*132 + r] = v.x;
            Ast[(k4+1)*132 + r] = v.y;
            Ast[(k4+2)*132 + r] = v.z;
            Ast[(k4+3)*132 + r] = v.w;
        }
        #pragma unroll
        for (int it = 0; it < 8; it++) {
            int idx = tid + it*128;           // float4 index into 64x64 W
            float4 v = *(const float4*)(W + idx*4);
            float4 o;
            o.x = sc*v.x; o.y = sc*v.y; o.z = sc*v.z; o.w = sc*v.w;
            if (W2) {
                float4 v2 = *(const float4*)(W2 + idx*4);
                o.x += sc2*v2.x; o.y += sc2*v2.y; o.z += sc2*v2.z; o.w += sc2*v2.w;
            }
            // identity fold: element (k,n) diagonal add
            int kk = idx >> 4;
            int dcol = kk - ((idx & 15) * 4);
            if (dg != 0.f && dcol >= 0 && dcol < 4) ((float*)&o)[dcol] += dg;
            *(float4*)(Ws + idx*4) = o;
        }
        __syncthreads();
        #pragma unroll 8
        for (int k = 0; k < 64; k++) {
            float4 a0 = *(const float4*)(Ast + k*132 + tx*8);
            float4 a1 = *(const float4*)(Ast + k*132 + tx*8 + 4);
            float4 b0 = *(const float4*)(Ws + k*64 + ty*8);
            float4 b1 = *(const float4*)(Ws + k*64 + ty*8 + 4);
            float a[8] = {a0.x,a0.y,a0.z,a0.w,a1.x,a1.y,a1.z,a1.w};
            float b[8] = {b0.x,b0.y,b0.z,b0.w,b1.x,b1.y,b1.z,b1.w};
            #pragma unroll
            for (int m = 0; m < 8; m++)
                #pragma unroll
                for (int n = 0; n < 8; n++)
                    acc[m][n] += a[m]*b[n];
        }
    }
    float bias[8] = {0,0,0,0,0,0,0,0};
    if (J.biasStep >= 0) {
        #pragma unroll
        for (int n = 0; n < 8; n++) bias[n] = d_bias[J.biasStep][ty*8 + n];
    }
    #pragma unroll
    for (int m = 0; m < 8; m++) {
        int gr = row0 + tx*8 + m;
        if (gr < Nn) {
            float* Dp = J.D + (size_t)gr*Cc + ty*8;
            *(float4*)Dp     = make_float4(acc[m][0]+bias[0],acc[m][1]+bias[1],
                                           acc[m][2]+bias[2],acc[m][3]+bias[3]);
            *(float4*)(Dp+4) = make_float4(acc[m][4]+bias[4],acc[m][5]+bias[5],
                                           acc[m][6]+bias[6],acc[m][7]+bias[7]);
        }
    }
}

// ---------------- GAT attention scalars ----------------
__global__ void rowdot_kernel(const float* ga_src, const float* ga_dst, int ko)
{
    int j = blockIdx.y;
    int k = ko + j;
    int gw = (blockIdx.x*blockDim.x + threadIdx.x) >> 5;
    if (gw >= Nn) return;
    int lane = threadIdx.x & 31;
    float2 h  = *(const float2*)(d_hw[j] + (size_t)gw*Cc + 2*lane);
    float2 as = *(const float2*)(ga_src + k*Cc + 2*lane);
    float2 ad = *(const float2*)(ga_dst + k*Cc + 2*lane);
    float s1 = h.x*as.x + h.y*as.y;
    float s2 = h.x*ad.x + h.y*ad.y;
    #pragma unroll
    for (int off = 16; off > 0; off >>= 1) {
        s1 += __shfl_xor_sync(0xffffffffu, s1, off);
        s2 += __shfl_xor_sync(0xffffffffu, s2, off);
    }
    if (lane == 0) { d_asrc[j][gw] = s1; d_adst[j][gw] = s2; }
}

// ---------------- SAGE mean aggregate: 4 edges x 8 lanes ----------------
__global__ void sage_agg_kernel(float* agg, const float* h)
{
    int gw = (blockIdx.x*blockDim.x + threadIdx.x) >> 5;
    if (gw >= Nn) return;
    int lane = threadIdx.x & 31;
    int g = lane >> 3, r = lane & 7;
    int v = gw;
    int beg = d_rowptr[v], end = d_rowptr[v+1];
    float4 a0 = make_float4(0,0,0,0), a1 = make_float4(0,0,0,0);
    for (int e0 = beg; e0 < end; e0 += 4) {
        int idx = e0 + g;
        if (idx < end) {
            int s = d_csrc[idx];
            const float* hp = h + (size_t)s*Cc + r*8;
            float4 p0 = *(const float4*)hp;
            float4 p1 = *(const float4*)(hp+4);
            a0.x += p0.x; a0.y += p0.y; a0.z += p0.z; a0.w += p0.w;
            a1.x += p1.x; a1.y += p1.y; a1.z += p1.z; a1.w += p1.w;
        }
    }
    #pragma unroll
    for (int off = 8; off <= 16; off <<= 1) {
        a0.x += __shfl_xor_sync(0xffffffffu, a0.x, off);
        a0.y += __shfl_xor_sync(0xffffffffu, a0.y, off);
        a0.z += __shfl_xor_sync(0xffffffffu, a0.z, off);
        a0.w += __shfl_xor_sync(0xffffffffu, a0.w, off);
        a1.x += __shfl_xor_sync(0xffffffffu, a1.x, off);
        a1.y += __shfl_xor_sync(0xffffffffu, a1.y, off);
        a1.z += __shfl_xor_sync(0xffffffffu, a1.z, off);
        a1.w += __shfl_xor_sync(0xffffffffu, a1.w, off);
    }
    if (g == 0) {
        float ci = d_cntinv[v];
        float* ap = agg + (size_t)v*Cc + r*8;
        *(float4*)ap     = make_float4(a0.x*ci, a0.y*ci, a0.z*ci, a0.w*ci);
        *(float4*)(ap+4) = make_float4(a1.x*ci, a1.y*ci, a1.z*ci, a1.w*ci);
    }
}

// ---------------- GCN aggregate: 4 edges x 8 lanes ----------------
__global__ void gcn_agg_kernel(float* S)
{
    int gw = (blockIdx.x*blockDim.x + threadIdx.x) >> 5;
    if (gw >= Nn) return;
    int lane = threadIdx.x & 31;
    int g = lane >> 3, r = lane & 7;
    int v = gw;
    int beg = d_rowptr[v], end = d_rowptr[v+1];
    float4 a0 = make_float4(0,0,0,0), a1 = make_float4(0,0,0,0);
    for (int e0 = beg; e0 < end; e0 += 4) {
        int idx = e0 + g;
        if (idx < end) {
            int s = d_csrc[idx];
            float cf = d_dinv[s];
            const float* hp = d_P + (size_t)s*Cc + r*8;
            float4 p0 = *(const float4*)hp;
            float4 p1 = *(const float4*)(hp+4);
            a0.x += cf*p0.x; a0.y += cf*p0.y; a0.z += cf*p0.z; a0.w += cf*p0.w;
            a1.x += cf*p1.x; a1.y += cf*p1.y; a1.z += cf*p1.z; a1.w += cf*p1.w;
        }
    }
    #pragma unroll
    for (int off = 8; off <= 16; off <<= 1) {
        a0.x += __shfl_xor_sync(0xffffffffu, a0.x, off);
        a0.y += __shfl_xor_sync(0xffffffffu, a0.y, off);
        a0.z += __shfl_xor_sync(0xffffffffu, a0.z, off);
        a0.w += __shfl_xor_sync(0xffffffffu, a0.w, off);
        a1.x += __shfl_xor_sync(0xffffffffu, a1.x, off);
        a1.y += __shfl_xor_sync(0xffffffffu, a1.y, off);
        a1.z += __shfl_xor_sync(0xffffffffu, a1.z, off);
        a1.w += __shfl_xor_sync(0xffffffffu, a1.w, off);
    }
    if (g == 0) {
        float dv = d_dinv[v];
        float dvv = dv*dv;
        const float* pp = d_P + (size_t)v*Cc + r*8;
        float4 p0 = *(const float4*)pp;
        float4 p1 = *(const float4*)(pp+4);
        float* Sp = S + (size_t)v*Cc + r*8;
        float4 s0 = *(float4*)Sp;
        float4 s1 = *(float4*)(Sp+4);
        s0.x += dv*a0.x + dvv*p0.x; s0.y += dv*a0.y + dvv*p0.y;
        s0.z += dv*a0.z + dvv*p0.z; s0.w += dv*a0.w + dvv*p0.w;
        s1.x += dv*a1.x + dvv*p1.x; s1.y += dv*a1.y + dvv*p1.y;
        s1.z += dv*a1.z + dvv*p1.z; s1.w += dv*a1.w + dvv*p1.w;
        *(float4*)Sp     = s0;
        *(float4*)(Sp+4) = s1;
    }
}

// ---------------- GAT: single-pass softmax (centered at eself), 4 edges x 8 lanes ----
__global__ void gat_agg_kernel(float* S, int ko, int nj)
{
    int gw = (blockIdx.x*blockDim.x + threadIdx.x) >> 5;
    if (gw >= Nn) return;
    int lane = threadIdx.x & 31;
    int g = lane >> 3, r = lane & 7;
    int v = gw;
    int beg = d_rowptr[v], end = d_rowptr[v+1];
    float4 t0 = make_float4(0,0,0,0), t1 = make_float4(0,0,0,0);
    for (int j = 0; j < nj; j++) {
        const float* hw = d_hw[j];
        const float* as = d_asrc[j];
        float adv = d_adst[j][v];
        float e0s = as[v] + adv;
        float m = e0s > 0.f ? e0s : 0.2f*e0s;   // softmax shift = self energy
        float denom = 0.f;
        float4 a0 = make_float4(0,0,0,0), a1 = make_float4(0,0,0,0);
        if (g == 0) {
            denom = 1.f;                         // exp(m - m)
            const float* hp = hw + (size_t)v*Cc + r*8;
            a0 = *(const float4*)hp;
            a1 = *(const float4*)(hp+4);
        }
        for (int e0 = beg; e0 < end; e0 += 4) {
            int idx = e0 + g;
            bool valid = idx < end;
            int s = 0;
            if (valid) s = d_csrc[idx];
            float p = 0.f;
            if (valid && r == 0) {
                float tv = as[s] + adv;
                tv = tv > 0.f ? tv : 0.2f*tv;
                p = __expf(tv - m);
            }
            p = __shfl_sync(0xffffffffu, p, lane & 24);   // broadcast within sub-warp
            if (valid) {
                const float* hp = hw + (size_t)s*Cc + r*8;
                float4 p0 = *(const float4*)hp;
                float4 p1 = *(const float4*)(hp+4);
                a0.x += p*p0.x; a0.y += p*p0.y; a0.z += p*p0.z; a0.w += p*p0.w;
                a1.x += p*p1.x; a1.y += p*p1.y; a1.z += p*p1.z; a1.w += p*p1.w;
                denom += p;
            }
        }
        #pragma unroll
        for (int off = 8; off <= 16; off <<= 1) {
            denom += __shfl_xor_sync(0xffffffffu, denom, off);
            a0.x += __shfl_xor_sync(0xffffffffu, a0.x, off);
            a0.y += __shfl_xor_sync(0xffffffffu, a0.y, off);
            a0.z += __shfl_xor_sync(0xffffffffu, a0.z, off);
            a0.w += __shfl_xor_sync(0xffffffffu, a0.w, off);
            a1.x += __shfl_xor_sync(0xffffffffu, a1.x, off);
            a1.y += __shfl_xor_sync(0xffffffffu, a1.y, off);
            a1.z += __shfl_xor_sync(0xffffffffu, a1.z, off);
            a1.w += __shfl_xor_sync(0xffffffffu, a1.w, off);
        }
        float wcoef = d_w[ko+j][2] / denom;
        t0.x += wcoef*a0.x; t0.y += wcoef*a0.y; t0.z += wcoef*a0.z; t0.w += wcoef*a0.w;
        t1.x += wcoef*a1.x; t1.y += wcoef*a1.y; t1.z += wcoef*a1.z; t1.w += wcoef*a1.w;
    }
    if (g == 0) {
        float* Sp = S + (size_t)v*Cc + r*8;
        float4 s0 = *(float4*)Sp;
        float4 s1 = *(float4*)(Sp+4);
        s0.x += t0.x; s0.y += t0.y; s0.z += t0.z; s0.w += t0.w;
        s1.x += t1.x; s1.y += t1.y; s1.z += t1.z; s1.w += t1.w;
        *(float4*)Sp     = s0;
        *(float4*)(Sp+4) = s1;
    }
}

// ---------------- output ----------------
__global__ void final_kernel(float* out)
{
    int idx = blockIdx.x*blockDim.x + threadIdx.x;
    if (idx >= NC) return;
    out[idx] = 0.25f*(d_s[0][idx] + d_s[1][idx] + d_s[2][idx] + d_s[3][idx]);
}

// ---------------- host orchestration ----------------
extern "C" void kernel_launch(void* const* d_in, const int* in_sizes, int n_in,
                              void* d_out, int out_size)
{
    const float* x       = (const float*)d_in[0];
    const int*   ei      = (const int*)d_in[1];     // int32
    const float* alphas  = (const float*)d_in[2];
    const float* gcn_W   = (const float*)d_in[3];
    const float* gcn_b   = (const float*)d_in[4];
    const float* sage_Wl = (const float*)d_in[5];
    const float* sage_Wr = (const float*)d_in[6];
    const float* sage_b  = (const float*)d_in[7];
    const float* gat_W   = (const float*)d_in[8];
    const float* ga_src  = (const float*)d_in[9];
    const float* ga_dst  = (const float*)d_in[10];
    const float* gat_b   = (const float*)d_in[11];
    float* out = (float*)d_out;
    (void)in_sizes; (void)n_in; (void)out_size;

    float *sbase, *Pp, *hwbase, *aggbase;
    cudaGetSymbolAddress((void**)&sbase,   d_s);
    cudaGetSymbolAddress((void**)&Pp,      d_P);
    cudaGetSymbolAddress((void**)&hwbase,  d_hw);
    cudaGetSymbolAddress((void**)&aggbase, d_agg);

    const int SMEMSZ = (64*132 + 64*64) * 4;   // 50176 B
    cudaFuncSetAttribute(gemm_kernel, cudaFuncAttributeMaxDynamicSharedMemorySize, SMEMSZ);

    const int NBLK = (Nn + 1023)/1024;   // 49

    zero_indeg_kernel<<<(Nn+511)/512,512>>>();
    prep_w_kernel<<<1,256>>>(alphas, gcn_b, sage_b, gat_b);
    degree_kernel<<<(Ee+255)/256,256>>>(ei);
    scan1_kernel<<<NBLK,1024>>>();
    scan2_kernel<<<1,64>>>(NBLK);
    scan3_kernel<<<NBLK,1024>>>();
    fill_kernel<<<(Ee+255)/256,256>>>(ei);
    sage_agg_kernel<<<6250,256>>>(aggbase, x);

    const int koff[4] = {0,2,5,9};
    for (int step = 0; step < 4; step++) {
        int nj = step + 2;
        int ko = koff[step];
        if (step >= 1)
            sage_agg_kernel<<<6250,256>>>(aggbase + (size_t)step*NC,
                                          sbase + (size_t)(step-1)*NC);

        GArgs ga;
        // job0: combined GCN input P
        {
            GJob& jb = ga.job[0];
            jb.D = Pp; jb.biasStep = -1;
            int n = 0;
            jb.t[n++] = GTerm{ x, gcn_W + (size_t)ko*4096, gcn_W + (size_t)(ko+1)*4096,
                               ko, 0, ko+1, 0 };
            for (int j = 2; j < nj; j++)
                jb.t[n++] = GTerm{ sbase + (size_t)(j-2)*NC, gcn_W + (size_t)(ko+j)*4096,
                                   nullptr, ko+j, 0, -1, 0 };
            jb.nt = n;
        }
        // job1: SAGE + identity(diag) + bias -> new state S (first writer)
        {
            GJob& jb = ga.job[1];
            jb.D = sbase + (size_t)step*NC; jb.biasStep = step;
            int n = 0;
            jb.t[n++] = GTerm{ aggbase, sage_Wl + (size_t)ko*4096,
                               sage_Wl + (size_t)(ko+1)*4096, ko, 1, ko+1, 0 };
            jb.t[n++] = GTerm{ x, sage_Wr + (size_t)ko*4096,
                               sage_Wr + (size_t)(ko+1)*4096, ko, 1, ko+1, 1 };
            for (int j = 2; j < nj; j++) {
                jb.t[n++] = GTerm{ aggbase + (size_t)(j-1)*NC,
                                   sage_Wl + (size_t)(ko+j)*4096, nullptr, ko+j, 1, -1, 0 };
                jb.t[n++] = GTerm{ sbase + (size_t)(j-2)*NC,
                                   sage_Wr + (size_t)(ko+j)*4096, nullptr, ko+j, 1, -1, 1 };
            }
            jb.nt = n;
        }
        // jobs 2..: GAT hw_j
        for (int j = 0; j < nj; j++) {
            const float* st = (j <= 1) ? x : sbase + (size_t)(j-2)*NC;
            ga.job[2+j].D = hwbase + (size_t)j*NC; ga.job[2+j].nt = 1;
            ga.job[2+j].biasStep = -1;
            ga.job[2+j].t[0] = GTerm{ st, gat_W + (size_t)(ko+j)*4096, nullptr, -1, 0, -1, 0 };
        }
        gemm_kernel<<<dim3(391, 2+nj), 128, SMEMSZ>>>(ga);

        rowdot_kernel<<<dim3(6250, nj), 256>>>(ga_src, ga_dst, ko);
        gcn_agg_kernel<<<6250,256>>>(sbase + (size_t)step*NC);
        gat_agg_kernel<<<6250,256>>>(sbase + (size_t)step*NC, ko, nj);
    }
    final_kernel<<<6250,512>>>(out);
}

// round 9
// speedup vs baseline: 2.1991x; 1.2964x over previous
#include <cuda_runtime.h>
#include <cuda_bf16.h>
#include <math.h>

#define Nn 50000
#define Cc 64
#define Ee 800000
#define NC (Nn*Cc)

// ---------------- device scratch ----------------
__device__ float d_s[4][NC];        // states 2..5
__device__ float d_P[NC];           // combined GCN input per step
__device__ float d_hw[5][NC];       // GAT hw_j per step
__device__ float d_agg[4][NC];      // SAGE mean aggregates
__device__ float d_asrc[5][Nn];
__device__ float d_adst[5][Nn];
__device__ int   d_indeg[Nn];
__device__ int   d_rowptr[Nn+1];
__device__ int   d_fill[Nn];
__device__ int   d_csrc[Ee];
__device__ float d_dinv[Nn];
__device__ float d_cntinv[Nn];
__device__ float d_w[14][5];
__device__ float d_bias[4][Cc];
__device__ int   d_bsum[64];
__device__ int   d_boff[64];

__global__ void zero_indeg_kernel()
{
    int i = blockIdx.x*blockDim.x + threadIdx.x;
    if (i < Nn) d_indeg[i] = 0;
}

__global__ void prep_w_kernel(const float* alphas, const float* gcn_b,
                              const float* sage_b, const float* gat_b)
{
    int t = threadIdx.x;
    if (t < 14) {
        float v[5]; float m = -1e30f;
        for (int i = 0; i < 5; i++) { v[i] = alphas[t*5+i]; m = fmaxf(m, v[i]); }
        float s = 0.f;
        for (int i = 0; i < 5; i++) { v[i] = expf(v[i]-m); s += v[i]; }
        for (int i = 0; i < 5; i++) d_w[t][i] = v[i]/s;
    }
    __syncthreads();
    int step = t >> 6, c = t & 63;
    const int koff[4] = {0,2,5,9};
    float b = 0.f;
    for (int j = 0; j < step+2; j++) {
        int k = koff[step] + j;
        b += d_w[k][0]*gcn_b[k*Cc+c] + d_w[k][1]*sage_b[k*Cc+c] + d_w[k][2]*gat_b[k*Cc+c];
    }
    d_bias[step][c] = b;
}

// ---------------- CSR construction (edge_index is int32) ----
__global__ void degree_kernel(const int* ei)
{
    int e = blockIdx.x*blockDim.x + threadIdx.x;
    if (e < Ee) {
        int d = ei[Ee + e];
        if ((unsigned)d < (unsigned)Nn) atomicAdd(&d_indeg[d], 1);
    }
}

__global__ void scan1_kernel()
{
    __shared__ int sh[32];
    int b = blockIdx.x, t = threadIdx.x;
    int i = b*1024 + t;
    int v = (i < Nn) ? d_indeg[i] : 0;
    #pragma unroll
    for (int off = 16; off > 0; off >>= 1) v += __shfl_down_sync(0xffffffffu, v, off);
    if ((t & 31) == 0) sh[t >> 5] = v;
    __syncthreads();
    if (t < 32) {
        int s = sh[t];
        #pragma unroll
        for (int off = 16; off > 0; off >>= 1) s += __shfl_down_sync(0xffffffffu, s, off);
        if (t == 0) d_bsum[b] = s;
    }
}

__global__ void scan2_kernel(int nblocks)
{
    __shared__ int sh[64];
    int t = threadIdx.x;
    int v = (t < nblocks) ? d_bsum[t] : 0;
    sh[t] = v;
    __syncthreads();
    #pragma unroll
    for (int off = 1; off < 64; off <<= 1) {
        int xv = (t >= off) ? sh[t-off] : 0;
        __syncthreads();
        sh[t] += xv;
        __syncthreads();
    }
    if (t < nblocks) d_boff[t] = sh[t] - v;
}

__global__ void scan3_kernel()
{
    __shared__ int sh[1024];
    int b = blockIdx.x, t = threadIdx.x;
    int i = b*1024 + t;
    int v = (i < Nn) ? d_indeg[i] : 0;
    sh[t] = v;
    __syncthreads();
    #pragma unroll
    for (int off = 1; off < 1024; off <<= 1) {
        int xv = (t >= off) ? sh[t-off] : 0;
        __syncthreads();
        sh[t] += xv;
        __syncthreads();
    }
    if (i < Nn) {
        int r = d_boff[b] + sh[t] - v;
        d_rowptr[i] = r;
        d_fill[i]   = r;
        d_dinv[i]   = rsqrtf((float)(v+1));
        d_cntinv[i] = 1.0f / (float)(v > 0 ? v : 1);
        if (i == Nn-1) d_rowptr[Nn] = r + v;
    }
}

__global__ void fill_kernel(const int* ei)
{
    int e = blockIdx.x*blockDim.x + threadIdx.x;
    if (e < Ee) {
        int s = ei[e];
        int d = ei[Ee + e];
        if ((unsigned)s < (unsigned)Nn && (unsigned)d < (unsigned)Nn) {
            int pos = atomicAdd(&d_fill[d], 1);
            if ((unsigned)pos < (unsigned)Ee) d_csrc[pos] = s;
        }
    }
}

// ---------------- multi-job GEMM: tensor cores (bf16 3-term split) ----------------
struct GTerm { const float* A; const float* W; const float* W2; int wk; int wcol; int wk2; int addDiag; };
struct GJob  { float* D; int nt; int biasStep; GTerm t[10]; };
struct GArgs { GJob job[7]; };

__device__ __forceinline__ void split2(float2 v, unsigned &hi, unsigned &lo)
{
    __nv_bfloat162 h = __float22bfloat162_rn(v);
    float2 hf = __bfloat1622float2(h);
    __nv_bfloat162 l = __float22bfloat162_rn(make_float2(v.x - hf.x, v.y - hf.y));
    hi = *(unsigned*)&h;
    lo = *(unsigned*)&l;
}

__device__ __forceinline__ void mma16816(float* d, const unsigned* a, const unsigned* b)
{
    asm volatile(
        "mma.sync.aligned.m16n8k16.row.col.f32.bf16.bf16.f32 "
        "{%0,%1,%2,%3},{%4,%5,%6,%7},{%8,%9},{%0,%1,%2,%3};"
        : "+f"(d[0]), "+f"(d[1]), "+f"(d[2]), "+f"(d[3])
        : "r"(a[0]), "r"(a[1]), "r"(a[2]), "r"(a[3]), "r"(b[0]), "r"(b[1]));
}

// CTA: 256 threads = 8 warps; tile = 128 rows x 64 cols; warp = 16 rows.
// smem: Ws fp32 [64][64] (16KB) + WH frag [4ks][8nt][32lane][2] (8KB) + WL (8KB)
__global__ void gemm_kernel(GArgs args)
{
    extern __shared__ float sm[];
    float*    Ws = sm;                         // 4096 floats
    unsigned* WH = (unsigned*)(sm + 4096);     // 2048 u32
    unsigned* WL = WH + 2048;                  // 2048 u32
    const GJob& J = args.job[blockIdx.y];
    int tid = threadIdx.x;
    int w = tid >> 5, l = tid & 31;
    int g = l >> 2, t4 = l & 3;
    int row0 = blockIdx.x * 128;
    int r0g = row0 + w*16 + g;
    int r1g = r0g + 8;

    float d[8][4];
    #pragma unroll
    for (int nt = 0; nt < 8; nt++)
        #pragma unroll
        for (int i = 0; i < 4; i++) d[nt][i] = 0.f;

    for (int tm = 0; tm < J.nt; tm++) {
        const float* A  = J.t[tm].A;
        const float* W  = J.t[tm].W;
        const float* W2 = J.t[tm].W2;
        float sc  = (J.t[tm].wk  >= 0) ? d_w[J.t[tm].wk ][J.t[tm].wcol] : 1.0f;
        float sc2 = (J.t[tm].wk2 >= 0) ? d_w[J.t[tm].wk2][J.t[tm].wcol] : 0.0f;
        float dg = 0.f;
        if (J.t[tm].addDiag) {
            dg = d_w[J.t[tm].wk][3];
            if (J.t[tm].wk2 >= 0) dg += d_w[J.t[tm].wk2][3];
        }
        __syncthreads();
        // W fp32 -> smem (scaled, merged, diag-folded)
        #pragma unroll
        for (int it = 0; it < 4; it++) {
            int idx = tid + it*256;           // float4 index into 64x64
            float4 v = *(const float4*)(W + idx*4);
            float4 o;
            o.x = sc*v.x; o.y = sc*v.y; o.z = sc*v.z; o.w = sc*v.w;
            if (W2) {
                float4 v2 = *(const float4*)(W2 + idx*4);
                o.x += sc2*v2.x; o.y += sc2*v2.y; o.z += sc2*v2.z; o.w += sc2*v2.w;
            }
            int kk = idx >> 4;
            int dcol = kk - ((idx & 15) * 4);
            if (dg != 0.f && dcol >= 0 && dcol < 4) ((float*)&o)[dcol] += dg;
            *(float4*)(Ws + idx*4) = o;
        }
        __syncthreads();
        // build B fragments (hi/lo) cooperatively: 1024 (ks,nt,lane) slots
        #pragma unroll
        for (int it = 0; it < 4; it++) {
            int i = tid + it*256;
            int ks = i >> 8, nt = (i >> 5) & 7, ll = i & 31;
            int tt = ll & 3, gg = ll >> 2;
            int n = nt*8 + gg;
            #pragma unroll
            for (int r = 0; r < 2; r++) {
                int k0 = ks*16 + r*8 + 2*tt;
                float2 f = make_float2(Ws[k0*64 + n], Ws[(k0+1)*64 + n]);
                unsigned hb, lb;
                split2(f, hb, lb);
                int slot = ((ks*8 + nt)*32 + ll)*2 + r;
                WH[slot] = hb;
                WL[slot] = lb;
            }
        }
        __syncthreads();
        // compute: per warp, K-loop of 4 x k16
        #pragma unroll
        for (int ks = 0; ks < 4; ks++) {
            float2 v00 = make_float2(0,0), v01 = v00, v10 = v00, v11 = v00;
            if (r0g < Nn) {
                const float2* Ar = (const float2*)(A + (size_t)r0g*Cc);
                v00 = Ar[ks*8 + t4];
                v01 = Ar[ks*8 + 4 + t4];
            }
            if (r1g < Nn) {
                const float2* Ar = (const float2*)(A + (size_t)r1g*Cc);
                v10 = Ar[ks*8 + t4];
                v11 = Ar[ks*8 + 4 + t4];
            }
            unsigned ah[4], al[4];
            split2(v00, ah[0], al[0]);
            split2(v10, ah[1], al[1]);
            split2(v01, ah[2], al[2]);
            split2(v11, ah[3], al[3]);
            #pragma unroll
            for (int nt = 0; nt < 8; nt++) {
                int slot = ((ks*8 + nt)*32 + l)*2;
                unsigned bh[2], bl[2];
                *(double*)bh = *(const double*)(WH + slot);
                *(double*)bl = *(const double*)(WL + slot);
                mma16816(d[nt], ah, bh);
                mma16816(d[nt], ah, bl);
                mma16816(d[nt], al, bh);
            }
        }
    }
    // epilogue: bias + store
    float2 b0s[8], b1s[8];
    #pragma unroll
    for (int nt = 0; nt < 8; nt++) {
        b0s[nt] = make_float2(0,0);
        if (J.biasStep >= 0) {
            int col = nt*8 + 2*t4;
            b0s[nt].x = d_bias[J.biasStep][col];
            b0s[nt].y = d_bias[J.biasStep][col+1];
        }
        b1s[nt] = b0s[nt];
    }
    if (r0g < Nn) {
        float* Dp = J.D + (size_t)r0g*Cc;
        #pragma unroll
        for (int nt = 0; nt < 8; nt++) {
            int col = nt*8 + 2*t4;
            *(float2*)(Dp + col) = make_float2(d[nt][0]+b0s[nt].x, d[nt][1]+b0s[nt].y);
        }
    }
    if (r1g < Nn) {
        float* Dp = J.D + (size_t)r1g*Cc;
        #pragma unroll
        for (int nt = 0; nt < 8; nt++) {
            int col = nt*8 + 2*t4;
            *(float2*)(Dp + col) = make_float2(d[nt][2]+b1s[nt].x, d[nt][3]+b1s[nt].y);
        }
    }
}

// ---------------- GAT attention scalars ----------------
__global__ void rowdot_kernel(const float* ga_src, const float* ga_dst, int ko)
{
    int j = blockIdx.y;
    int k = ko + j;
    int gw = (blockIdx.x*blockDim.x + threadIdx.x) >> 5;
    if (gw >= Nn) return;
    int lane = threadIdx.x & 31;
    float2 h  = *(const float2*)(d_hw[j] + (size_t)gw*Cc + 2*lane);
    float2 as = *(const float2*)(ga_src + k*Cc + 2*lane);
    float2 ad = *(const float2*)(ga_dst + k*Cc + 2*lane);
    float s1 = h.x*as.x + h.y*as.y;
    float s2 = h.x*ad.x + h.y*ad.y;
    #pragma unroll
    for (int off = 16; off > 0; off >>= 1) {
        s1 += __shfl_xor_sync(0xffffffffu, s1, off);
        s2 += __shfl_xor_sync(0xffffffffu, s2, off);
    }
    if (lane == 0) { d_asrc[j][gw] = s1; d_adst[j][gw] = s2; }
}

// ---------------- SAGE mean aggregate: 4 edges x 8 lanes ----------------
__global__ void sage_agg_kernel(float* agg, const float* h)
{
    int gw = (blockIdx.x*blockDim.x + threadIdx.x) >> 5;
    if (gw >= Nn) return;
    int lane = threadIdx.x & 31;
    int g = lane >> 3, r = lane & 7;
    int v = gw;
    int beg = d_rowptr[v], end = d_rowptr[v+1];
    float4 a0 = make_float4(0,0,0,0), a1 = make_float4(0,0,0,0);
    for (int e0 = beg; e0 < end; e0 += 4) {
        int idx = e0 + g;
        if (idx < end) {
            int s = d_csrc[idx];
            const float* hp = h + (size_t)s*Cc + r*8;
            float4 p0 = *(const float4*)hp;
            float4 p1 = *(const float4*)(hp+4);
            a0.x += p0.x; a0.y += p0.y; a0.z += p0.z; a0.w += p0.w;
            a1.x += p1.x; a1.y += p1.y; a1.z += p1.z; a1.w += p1.w;
        }
    }
    #pragma unroll
    for (int off = 8; off <= 16; off <<= 1) {
        a0.x += __shfl_xor_sync(0xffffffffu, a0.x, off);
        a0.y += __shfl_xor_sync(0xffffffffu, a0.y, off);
        a0.z += __shfl_xor_sync(0xffffffffu, a0.z, off);
        a0.w += __shfl_xor_sync(0xffffffffu, a0.w, off);
        a1.x += __shfl_xor_sync(0xffffffffu, a1.x, off);
        a1.y += __shfl_xor_sync(0xffffffffu, a1.y, off);
        a1.z += __shfl_xor_sync(0xffffffffu, a1.z, off);
        a1.w += __shfl_xor_sync(0xffffffffu, a1.w, off);
    }
    if (g == 0) {
        float ci = d_cntinv[v];
        float* ap = agg + (size_t)v*Cc + r*8;
        *(float4*)ap     = make_float4(a0.x*ci, a0.y*ci, a0.z*ci, a0.w*ci);
        *(float4*)(ap+4) = make_float4(a1.x*ci, a1.y*ci, a1.z*ci, a1.w*ci);
    }
}

// ---------------- GCN aggregate: 4 edges x 8 lanes ----------------
__global__ void gcn_agg_kernel(float* S)
{
    int gw = (blockIdx.x*blockDim.x + threadIdx.x) >> 5;
    if (gw >= Nn) return;
    int lane = threadIdx.x & 31;
    int g = lane >> 3, r = lane & 7;
    int v = gw;
    int beg = d_rowptr[v], end = d_rowptr[v+1];
    float4 a0 = make_float4(0,0,0,0), a1 = make_float4(0,0,0,0);
    for (int e0 = beg; e0 < end; e0 += 4) {
        int idx = e0 + g;
        if (idx < end) {
            int s = d_csrc[idx];
            float cf = d_dinv[s];
            const float* hp = d_P + (size_t)s*Cc + r*8;
            float4 p0 = *(const float4*)hp;
            float4 p1 = *(const float4*)(hp+4);
            a0.x += cf*p0.x; a0.y += cf*p0.y; a0.z += cf*p0.z; a0.w += cf*p0.w;
            a1.x += cf*p1.x; a1.y += cf*p1.y; a1.z += cf*p1.z; a1.w += cf*p1.w;
        }
    }
    #pragma unroll
    for (int off = 8; off <= 16; off <<= 1) {
        a0.x += __shfl_xor_sync(0xffffffffu, a0.x, off);
        a0.y += __shfl_xor_sync(0xffffffffu, a0.y, off);
        a0.z += __shfl_xor_sync(0xffffffffu, a0.z, off);
        a0.w += __shfl_xor_sync(0xffffffffu, a0.w, off);
        a1.x += __shfl_xor_sync(0xffffffffu, a1.x, off);
        a1.y += __shfl_xor_sync(0xffffffffu, a1.y, off);
        a1.z += __shfl_xor_sync(0xffffffffu, a1.z, off);
        a1.w += __shfl_xor_sync(0xffffffffu, a1.w, off);
    }
    if (g == 0) {
        float dv = d_dinv[v];
        float dvv = dv*dv;
        const float* pp = d_P + (size_t)v*Cc + r*8;
        float4 p0 = *(const float4*)pp;
        float4 p1 = *(const float4*)(pp+4);
        float* Sp = S + (size_t)v*Cc + r*8;
        float4 s0 = *(float4*)Sp;
        float4 s1 = *(float4*)(Sp+4);
        s0.x += dv*a0.x + dvv*p0.x; s0.y += dv*a0.y + dvv*p0.y;
        s0.z += dv*a0.z + dvv*p0.z; s0.w += dv*a0.w + dvv*p0.w;
        s1.x += dv*a1.x + dvv*p1.x; s1.y += dv*a1.y + dvv*p1.y;
        s1.z += dv*a1.z + dvv*p1.z; s1.w += dv*a1.w + dvv*p1.w;
        *(float4*)Sp     = s0;
        *(float4*)(Sp+4) = s1;
    }
}

// ---------------- GAT: single-pass softmax (centered at eself), 4 edges x 8 lanes ----
__global__ void gat_agg_kernel(float* S, int ko, int nj)
{
    int gw = (blockIdx.x*blockDim.x + threadIdx.x) >> 5;
    if (gw >= Nn) return;
    int lane = threadIdx.x & 31;
    int g = lane >> 3, r = lane & 7;
    int v = gw;
    int beg = d_rowptr[v], end = d_rowptr[v+1];
    float4 t0 = make_float4(0,0,0,0), t1 = make_float4(0,0,0,0);
    for (int j = 0; j < nj; j++) {
        const float* hw = d_hw[j];
        const float* as = d_asrc[j];
        float adv = d_adst[j][v];
        float e0s = as[v] + adv;
        float m = e0s > 0.f ? e0s : 0.2f*e0s;
        float denom = 0.f;
        float4 a0 = make_float4(0,0,0,0), a1 = make_float4(0,0,0,0);
        if (g == 0) {
            denom = 1.f;
            const float* hp = hw + (size_t)v*Cc + r*8;
            a0 = *(const float4*)hp;
            a1 = *(const float4*)(hp+4);
        }
        for (int e0 = beg; e0 < end; e0 += 4) {
            int idx = e0 + g;
            bool valid = idx < end;
            int s = 0;
            if (valid) s = d_csrc[idx];
            float p = 0.f;
            if (valid && r == 0) {
                float tv = as[s] + adv;
                tv = tv > 0.f ? tv : 0.2f*tv;
                p = __expf(tv - m);
            }
            p = __shfl_sync(0xffffffffu, p, lane & 24);
            if (valid) {
                const float* hp = hw + (size_t)s*Cc + r*8;
                float4 p0 = *(const float4*)hp;
                float4 p1 = *(const float4*)(hp+4);
                a0.x += p*p0.x; a0.y += p*p0.y; a0.z += p*p0.z; a0.w += p*p0.w;
                a1.x += p*p1.x; a1.y += p*p1.y; a1.z += p*p1.z; a1.w += p*p1.w;
                denom += p;
            }
        }
        #pragma unroll
        for (int off = 8; off <= 16; off <<= 1) {
            denom += __shfl_xor_sync(0xffffffffu, denom, off);
            a0.x += __shfl_xor_sync(0xffffffffu, a0.x, off);
            a0.y += __shfl_xor_sync(0xffffffffu, a0.y, off);
            a0.z += __shfl_xor_sync(0xffffffffu, a0.z, off);
            a0.w += __shfl_xor_sync(0xffffffffu, a0.w, off);
            a1.x += __shfl_xor_sync(0xffffffffu, a1.x, off);
            a1.y += __shfl_xor_sync(0xffffffffu, a1.y, off);
            a1.z += __shfl_xor_sync(0xffffffffu, a1.z, off);
            a1.w += __shfl_xor_sync(0xffffffffu, a1.w, off);
        }
        float wcoef = d_w[ko+j][2] / denom;
        t0.x += wcoef*a0.x; t0.y += wcoef*a0.y; t0.z += wcoef*a0.z; t0.w += wcoef*a0.w;
        t1.x += wcoef*a1.x; t1.y += wcoef*a1.y; t1.z += wcoef*a1.z; t1.w += wcoef*a1.w;
    }
    if (g == 0) {
        float* Sp = S + (size_t)v*Cc + r*8;
        float4 s0 = *(float4*)Sp;
        float4 s1 = *(float4*)(Sp+4);
        s0.x += t0.x; s0.y += t0.y; s0.z += t0.z; s0.w += t0.w;
        s1.x += t1.x; s1.y += t1.y; s1.z += t1.z; s1.w += t1.w;
        *(float4*)Sp     = s0;
        *(float4*)(Sp+4) = s1;
    }
}

// ---------------- output ----------------
__global__ void final_kernel(float* out)
{
    int idx = blockIdx.x*blockDim.x + threadIdx.x;
    if (idx >= NC) return;
    out[idx] = 0.25f*(d_s[0][idx] + d_s[1][idx] + d_s[2][idx] + d_s[3][idx]);
}

// ---------------- host orchestration ----------------
extern "C" void kernel_launch(void* const* d_in, const int* in_sizes, int n_in,
                              void* d_out, int out_size)
{
    const float* x       = (const float*)d_in[0];
    const int*   ei      = (const int*)d_in[1];     // int32
    const float* alphas  = (const float*)d_in[2];
    const float* gcn_W   = (const float*)d_in[3];
    const float* gcn_b   = (const float*)d_in[4];
    const float* sage_Wl = (const float*)d_in[5];
    const float* sage_Wr = (const float*)d_in[6];
    const float* sage_b  = (const float*)d_in[7];
    const float* gat_W   = (const float*)d_in[8];
    const float* ga_src  = (const float*)d_in[9];
    const float* ga_dst  = (const float*)d_in[10];
    const float* gat_b   = (const float*)d_in[11];
    float* out = (float*)d_out;
    (void)in_sizes; (void)n_in; (void)out_size;

    float *sbase, *Pp, *hwbase, *aggbase;
    cudaGetSymbolAddress((void**)&sbase,   d_s);
    cudaGetSymbolAddress((void**)&Pp,      d_P);
    cudaGetSymbolAddress((void**)&hwbase,  d_hw);
    cudaGetSymbolAddress((void**)&aggbase, d_agg);

    const int SMEMSZ = 4096*4 + 2048*4*2;   // Ws fp32 + WH + WL = 32768 B
    cudaFuncSetAttribute(gemm_kernel, cudaFuncAttributeMaxDynamicSharedMemorySize, SMEMSZ);

    const int NBLK = (Nn + 1023)/1024;   // 49

    zero_indeg_kernel<<<(Nn+511)/512,512>>>();
    prep_w_kernel<<<1,256>>>(alphas, gcn_b, sage_b, gat_b);
    degree_kernel<<<(Ee+255)/256,256>>>(ei);
    scan1_kernel<<<NBLK,1024>>>();
    scan2_kernel<<<1,64>>>(NBLK);
    scan3_kernel<<<NBLK,1024>>>();
    fill_kernel<<<(Ee+255)/256,256>>>(ei);
    sage_agg_kernel<<<6250,256>>>(aggbase, x);

    const int koff[4] = {0,2,5,9};
    for (int step = 0; step < 4; step++) {
        int nj = step + 2;
        int ko = koff[step];
        if (step >= 1)
            sage_agg_kernel<<<6250,256>>>(aggbase + (size_t)step*NC,
                                          sbase + (size_t)(step-1)*NC);

        GArgs ga;
        // job0: combined GCN input P
        {
            GJob& jb = ga.job[0];
            jb.D = Pp; jb.biasStep = -1;
            int n = 0;
            jb.t[n++] = GTerm{ x, gcn_W + (size_t)ko*4096, gcn_W + (size_t)(ko+1)*4096,
                               ko, 0, ko+1, 0 };
            for (int j = 2; j < nj; j++)
                jb.t[n++] = GTerm{ sbase + (size_t)(j-2)*NC, gcn_W + (size_t)(ko+j)*4096,
                                   nullptr, ko+j, 0, -1, 0 };
            jb.nt = n;
        }
        // job1: SAGE + identity(diag) + bias -> new state S (first writer)
        {
            GJob& jb = ga.job[1];
            jb.D = sbase + (size_t)step*NC; jb.biasStep = step;
            int n = 0;
            jb.t[n++] = GTerm{ aggbase, sage_Wl + (size_t)ko*4096,
                               sage_Wl + (size_t)(ko+1)*4096, ko, 1, ko+1, 0 };
            jb.t[n++] = GTerm{ x, sage_Wr + (size_t)ko*4096,
                               sage_Wr + (size_t)(ko+1)*4096, ko, 1, ko+1, 1 };
            for (int j = 2; j < nj; j++) {
                jb.t[n++] = GTerm{ aggbase + (size_t)(j-1)*NC,
                                   sage_Wl + (size_t)(ko+j)*4096, nullptr, ko+j, 1, -1, 0 };
                jb.t[n++] = GTerm{ sbase + (size_t)(j-2)*NC,
                                   sage_Wr + (size_t)(ko+j)*4096, nullptr, ko+j, 1, -1, 1 };
            }
            jb.nt = n;
        }
        // jobs 2..: GAT hw_j
        for (int j = 0; j < nj; j++) {
            const float* st = (j <= 1) ? x : sbase + (size_t)(j-2)*NC;
            ga.job[2+j].D = hwbase + (size_t)j*NC; ga.job[2+j].nt = 1;
            ga.job[2+j].biasStep = -1;
            ga.job[2+j].t[0] = GTerm{ st, gat_W + (size_t)(ko+j)*4096, nullptr, -1, 0, -1, 0 };
        }
        gemm_kernel<<<dim3(391, 2+nj), 256, SMEMSZ>>>(ga);

        rowdot_kernel<<<dim3(6250, nj), 256>>>(ga_src, ga_dst, ko);
        gcn_agg_kernel<<<6250,256>>>(sbase + (size_t)step*NC);
        gat_agg_kernel<<<6250,256>>>(sbase + (size_t)step*NC, ko, nj);
    }
    final_kernel<<<6250,512>>>(out);
}

// round 12
// speedup vs baseline: 2.3414x; 1.0647x over previous
#include <cuda_runtime.h>
#include <cuda_bf16.h>
#include <math.h>

#define Nn 50000
#define Cc 64
#define Ee 800000
#define NC (Nn*Cc)

// ---------------- device scratch ----------------
__device__ float d_s[4][NC];                // states 2..5
__device__ float d_P[NC];                   // combined GCN input per step
__device__ __nv_bfloat16 d_hwb[5][NC];      // GAT hw_j per step (bf16 gather array)
__device__ float d_agg[4][NC];              // SAGE mean aggregates
__device__ float d_asrc[5][Nn];
__device__ float d_adst[5][Nn];
__device__ int   d_indeg[Nn];
__device__ int   d_rowptr[Nn+1];
__device__ int   d_fill[Nn];
__device__ int   d_csrc[Ee];
__device__ float d_dinv[Nn];
__device__ float d_cntinv[Nn];
__device__ float d_w[14][5];
__device__ float d_bias[4][Cc];
__device__ int   d_bsum[64];
__device__ int   d_boff[64];

__global__ void zero_indeg_kernel()
{
    int i = blockIdx.x*blockDim.x + threadIdx.x;
    if (i < Nn) d_indeg[i] = 0;
}

__global__ void prep_w_kernel(const float* alphas, const float* gcn_b,
                              const float* sage_b, const float* gat_b)
{
    int t = threadIdx.x;
    if (t < 14) {
        float v[5]; float m = -1e30f;
        for (int i = 0; i < 5; i++) { v[i] = alphas[t*5+i]; m = fmaxf(m, v[i]); }
        float s = 0.f;
        for (int i = 0; i < 5; i++) { v[i] = expf(v[i]-m); s += v[i]; }
        for (int i = 0; i < 5; i++) d_w[t][i] = v[i]/s;
    }
    __syncthreads();
    int step = t >> 6, c = t & 63;
    const int koff[4] = {0,2,5,9};
    float b = 0.f;
    for (int j = 0; j < step+2; j++) {
        int k = koff[step] + j;
        b += d_w[k][0]*gcn_b[k*Cc+c] + d_w[k][1]*sage_b[k*Cc+c] + d_w[k][2]*gat_b[k*Cc+c];
    }
    d_bias[step][c] = b;
}

// ---------------- CSR construction (edge_index is int32) ----
__global__ void degree_kernel(const int* ei)
{
    int e = blockIdx.x*blockDim.x + threadIdx.x;
    if (e < Ee) {
        int d = ei[Ee + e];
        if ((unsigned)d < (unsigned)Nn) atomicAdd(&d_indeg[d], 1);
    }
}

__global__ void scan1_kernel()
{
    __shared__ int sh[32];
    int b = blockIdx.x, t = threadIdx.x;
    int i = b*1024 + t;
    int v = (i < Nn) ? d_indeg[i] : 0;
    #pragma unroll
    for (int off = 16; off > 0; off >>= 1) v += __shfl_down_sync(0xffffffffu, v, off);
    if ((t & 31) == 0) sh[t >> 5] = v;
    __syncthreads();
    if (t < 32) {
        int s = sh[t];
        #pragma unroll
        for (int off = 16; off > 0; off >>= 1) s += __shfl_down_sync(0xffffffffu, s, off);
        if (t == 0) d_bsum[b] = s;
    }
}

__global__ void scan2_kernel(int nblocks)
{
    __shared__ int sh[64];
    int t = threadIdx.x;
    int v = (t < nblocks) ? d_bsum[t] : 0;
    sh[t] = v;
    __syncthreads();
    #pragma unroll
    for (int off = 1; off < 64; off <<= 1) {
        int xv = (t >= off) ? sh[t-off] : 0;
        __syncthreads();
        sh[t] += xv;
        __syncthreads();
    }
    if (t < nblocks) d_boff[t] = sh[t] - v;
}

__global__ void scan3_kernel()
{
    __shared__ int sh[1024];
    int b = blockIdx.x, t = threadIdx.x;
    int i = b*1024 + t;
    int v = (i < Nn) ? d_indeg[i] : 0;
    sh[t] = v;
    __syncthreads();
    #pragma unroll
    for (int off = 1; off < 1024; off <<= 1) {
        int xv = (t >= off) ? sh[t-off] : 0;
        __syncthreads();
        sh[t] += xv;
        __syncthreads();
    }
    if (i < Nn) {
        int r = d_boff[b] + sh[t] - v;
        d_rowptr[i] = r;
        d_fill[i]   = r;
        d_dinv[i]   = rsqrtf((float)(v+1));
        d_cntinv[i] = 1.0f / (float)(v > 0 ? v : 1);
        if (i == Nn-1) d_rowptr[Nn] = r + v;
    }
}

__global__ void fill_kernel(const int* ei)
{
    int e = blockIdx.x*blockDim.x + threadIdx.x;
    if (e < Ee) {
        int s = ei[e];
        int d = ei[Ee + e];
        if ((unsigned)s < (unsigned)Nn && (unsigned)d < (unsigned)Nn) {
            int pos = atomicAdd(&d_fill[d], 1);
            if ((unsigned)pos < (unsigned)Ee) d_csrc[pos] = s;
        }
    }
}

// ---------------- multi-job GEMM: tensor cores (bf16 3-term split) ----------------
// jobs: fp32 out (P, S) or bf16 out (GAT hw) with fused rowdot -> d_asrc/d_adst
struct GTerm { const float* A; const float* W; const float* W2; int wk; int wcol; int wk2; int addDiag; };
struct GJob  { float* D; int nt; int biasStep; int gatJ;
               const float* gasrc; const float* gadst; GTerm t[10]; };
struct GArgs { GJob job[7]; };

__device__ __forceinline__ void split2(float2 v, unsigned &hi, unsigned &lo)
{
    __nv_bfloat162 h = __float22bfloat162_rn(v);
    float2 hf = __bfloat1622float2(h);
    __nv_bfloat162 l = __float22bfloat162_rn(make_float2(v.x - hf.x, v.y - hf.y));
    hi = *(unsigned*)&h;
    lo = *(unsigned*)&l;
}

__device__ __forceinline__ void mma16816(float* d, const unsigned* a, const unsigned* b)
{
    asm volatile(
        "mma.sync.aligned.m16n8k16.row.col.f32.bf16.bf16.f32 "
        "{%0,%1,%2,%3},{%4,%5,%6,%7},{%8,%9},{%0,%1,%2,%3};"
        : "+f"(d[0]), "+f"(d[1]), "+f"(d[2]), "+f"(d[3])
        : "r"(a[0]), "r"(a[1]), "r"(a[2]), "r"(a[3]), "r"(b[0]), "r"(b[1]));
}

__global__ void gemm_kernel(GArgs args)
{
    extern __shared__ float sm[];
    float*    Ws = sm;                         // 4096 floats
    unsigned* WH = (unsigned*)(sm + 4096);     // 2048 u32
    unsigned* WL = WH + 2048;                  // 2048 u32
    const GJob& J = args.job[blockIdx.y];
    int tid = threadIdx.x;
    int w = tid >> 5, l = tid & 31;
    int g = l >> 2, t4 = l & 3;
    int row0 = blockIdx.x * 128;
    int r0g = row0 + w*16 + g;
    int r1g = r0g + 8;

    float d[8][4];
    #pragma unroll
    for (int nt = 0; nt < 8; nt++)
        #pragma unroll
        for (int i = 0; i < 4; i++) d[nt][i] = 0.f;

    for (int tm = 0; tm < J.nt; tm++) {
        const float* A  = J.t[tm].A;
        const float* W  = J.t[tm].W;
        const float* W2 = J.t[tm].W2;
        float sc  = (J.t[tm].wk  >= 0) ? d_w[J.t[tm].wk ][J.t[tm].wcol] : 1.0f;
        float sc2 = (J.t[tm].wk2 >= 0) ? d_w[J.t[tm].wk2][J.t[tm].wcol] : 0.0f;
        float dg = 0.f;
        if (J.t[tm].addDiag) {
            dg = d_w[J.t[tm].wk][3];
            if (J.t[tm].wk2 >= 0) dg += d_w[J.t[tm].wk2][3];
        }
        __syncthreads();
        #pragma unroll
        for (int it = 0; it < 4; it++) {
            int idx = tid + it*256;
            float4 v = *(const float4*)(W + idx*4);
            float4 o;
            o.x = sc*v.x; o.y = sc*v.y; o.z = sc*v.z; o.w = sc*v.w;
            if (W2) {
                float4 v2 = *(const float4*)(W2 + idx*4);
                o.x += sc2*v2.x; o.y += sc2*v2.y; o.z += sc2*v2.z; o.w += sc2*v2.w;
            }
            int kk = idx >> 4;
            int dcol = kk - ((idx & 15) * 4);
            if (dg != 0.f && dcol >= 0 && dcol < 4) ((float*)&o)[dcol] += dg;
            *(float4*)(Ws + idx*4) = o;
        }
        __syncthreads();
        #pragma unroll
        for (int it = 0; it < 4; it++) {
            int i = tid + it*256;
            int ks = i >> 8, nt = (i >> 5) & 7, ll = i & 31;
            int tt = ll & 3, gg = ll >> 2;
            int n = nt*8 + gg;
            #pragma unroll
            for (int r = 0; r < 2; r++) {
                int k0 = ks*16 + r*8 + 2*tt;
                float2 f = make_float2(Ws[k0*64 + n], Ws[(k0+1)*64 + n]);
                unsigned hb, lb;
                split2(f, hb, lb);
                int slot = ((ks*8 + nt)*32 + ll)*2 + r;
                WH[slot] = hb;
                WL[slot] = lb;
            }
        }
        __syncthreads();
        #pragma unroll
        for (int ks = 0; ks < 4; ks++) {
            float2 v00 = make_float2(0,0), v01 = v00, v10 = v00, v11 = v00;
            if (r0g < Nn) {
                const float2* Ar = (const float2*)(A + (size_t)r0g*Cc);
                v00 = Ar[ks*8 + t4];
                v01 = Ar[ks*8 + 4 + t4];
            }
            if (r1g < Nn) {
                const float2* Ar = (const float2*)(A + (size_t)r1g*Cc);
                v10 = Ar[ks*8 + t4];
                v11 = Ar[ks*8 + 4 + t4];
            }
            unsigned ah[4], al[4];
            split2(v00, ah[0], al[0]);
            split2(v10, ah[1], al[1]);
            split2(v01, ah[2], al[2]);
            split2(v11, ah[3], al[3]);
            #pragma unroll
            for (int nt = 0; nt < 8; nt++) {
                int slot = ((ks*8 + nt)*32 + l)*2;
                unsigned bh[2], bl[2];
                *(double*)bh = *(const double*)(WH + slot);
                *(double*)bl = *(const double*)(WL + slot);
                mma16816(d[nt], ah, bh);
                mma16816(d[nt], ah, bl);
                mma16816(d[nt], al, bh);
            }
        }
    }

    if (J.gatJ >= 0) {
        // fused rowdot: <hw_row, a_src>, <hw_row, a_dst> via t4-lane reduction
        float ss0 = 0.f, sd0 = 0.f, ss1 = 0.f, sd1 = 0.f;
        #pragma unroll
        for (int nt = 0; nt < 8; nt++) {
            int c = nt*8 + 2*t4;
            float as0 = J.gasrc[c], as1 = J.gasrc[c+1];
            float ad0 = J.gadst[c], ad1 = J.gadst[c+1];
            ss0 += d[nt][0]*as0 + d[nt][1]*as1;
            sd0 += d[nt][0]*ad0 + d[nt][1]*ad1;
            ss1 += d[nt][2]*as0 + d[nt][3]*as1;
            sd1 += d[nt][2]*ad0 + d[nt][3]*ad1;
        }
        #pragma unroll
        for (int off = 1; off <= 2; off <<= 1) {
            ss0 += __shfl_xor_sync(0xffffffffu, ss0, off);
            sd0 += __shfl_xor_sync(0xffffffffu, sd0, off);
            ss1 += __shfl_xor_sync(0xffffffffu, ss1, off);
            sd1 += __shfl_xor_sync(0xffffffffu, sd1, off);
        }
        if (t4 == 0) {
            if (r0g < Nn) { d_asrc[J.gatJ][r0g] = ss0; d_adst[J.gatJ][r0g] = sd0; }
            if (r1g < Nn) { d_asrc[J.gatJ][r1g] = ss1; d_adst[J.gatJ][r1g] = sd1; }
        }
        // bf16 store of hw
        __nv_bfloat16* Db = (__nv_bfloat16*)J.D;
        if (r0g < Nn) {
            __nv_bfloat16* Dp = Db + (size_t)r0g*Cc;
            #pragma unroll
            for (int nt = 0; nt < 8; nt++) {
                __nv_bfloat162 hb = __float22bfloat162_rn(make_float2(d[nt][0], d[nt][1]));
                *(unsigned*)(Dp + nt*8 + 2*t4) = *(unsigned*)&hb;
            }
        }
        if (r1g < Nn) {
            __nv_bfloat16* Dp = Db + (size_t)r1g*Cc;
            #pragma unroll
            for (int nt = 0; nt < 8; nt++) {
                __nv_bfloat162 hb = __float22bfloat162_rn(make_float2(d[nt][2], d[nt][3]));
                *(unsigned*)(Dp + nt*8 + 2*t4) = *(unsigned*)&hb;
            }
        }
    } else {
        float2 bs[8];
        #pragma unroll
        for (int nt = 0; nt < 8; nt++) {
            bs[nt] = make_float2(0,0);
            if (J.biasStep >= 0) {
                int col = nt*8 + 2*t4;
                bs[nt].x = d_bias[J.biasStep][col];
                bs[nt].y = d_bias[J.biasStep][col+1];
            }
        }
        if (r0g < Nn) {
            float* Dp = J.D + (size_t)r0g*Cc;
            #pragma unroll
            for (int nt = 0; nt < 8; nt++) {
                int col = nt*8 + 2*t4;
                *(float2*)(Dp + col) = make_float2(d[nt][0]+bs[nt].x, d[nt][1]+bs[nt].y);
            }
        }
        if (r1g < Nn) {
            float* Dp = J.D + (size_t)r1g*Cc;
            #pragma unroll
            for (int nt = 0; nt < 8; nt++) {
                int col = nt*8 + 2*t4;
                *(float2*)(Dp + col) = make_float2(d[nt][2]+bs[nt].x, d[nt][3]+bs[nt].y);
            }
        }
    }
}

// ---------------- SAGE mean aggregate: 4 edges x 8 lanes ----------------
__global__ void sage_agg_kernel(float* agg, const float* h)
{
    int gw = (blockIdx.x*blockDim.x + threadIdx.x) >> 5;
    if (gw >= Nn) return;
    int lane = threadIdx.x & 31;
    int g = lane >> 3, r = lane & 7;
    int v = gw;
    int beg = d_rowptr[v], end = d_rowptr[v+1];
    float4 a0 = make_float4(0,0,0,0), a1 = make_float4(0,0,0,0);
    for (int e0 = beg; e0 < end; e0 += 4) {
        int idx = e0 + g;
        if (idx < end) {
            int s = d_csrc[idx];
            const float* hp = h + (size_t)s*Cc + r*8;
            float4 p0 = *(const float4*)hp;
            float4 p1 = *(const float4*)(hp+4);
            a0.x += p0.x; a0.y += p0.y; a0.z += p0.z; a0.w += p0.w;
            a1.x += p1.x; a1.y += p1.y; a1.z += p1.z; a1.w += p1.w;
        }
    }
    #pragma unroll
    for (int off = 8; off <= 16; off <<= 1) {
        a0.x += __shfl_xor_sync(0xffffffffu, a0.x, off);
        a0.y += __shfl_xor_sync(0xffffffffu, a0.y, off);
        a0.z += __shfl_xor_sync(0xffffffffu, a0.z, off);
        a0.w += __shfl_xor_sync(0xffffffffu, a0.w, off);
        a1.x += __shfl_xor_sync(0xffffffffu, a1.x, off);
        a1.y += __shfl_xor_sync(0xffffffffu, a1.y, off);
        a1.z += __shfl_xor_sync(0xffffffffu, a1.z, off);
        a1.w += __shfl_xor_sync(0xffffffffu, a1.w, off);
    }
    if (g == 0) {
        float ci = d_cntinv[v];
        float* ap = agg + (size_t)v*Cc + r*8;
        *(float4*)ap     = make_float4(a0.x*ci, a0.y*ci, a0.z*ci, a0.w*ci);
        *(float4*)(ap+4) = make_float4(a1.x*ci, a1.y*ci, a1.z*ci, a1.w*ci);
    }
}

// ---------------- GCN aggregate: 4 edges x 8 lanes ----------------
__global__ void gcn_agg_kernel(float* S)
{
    int gw = (blockIdx.x*blockDim.x + threadIdx.x) >> 5;
    if (gw >= Nn) return;
    int lane = threadIdx.x & 31;
    int g = lane >> 3, r = lane & 7;
    int v = gw;
    int beg = d_rowptr[v], end = d_rowptr[v+1];
    float4 a0 = make_float4(0,0,0,0), a1 = make_float4(0,0,0,0);
    for (int e0 = beg; e0 < end; e0 += 4) {
        int idx = e0 + g;
        if (idx < end) {
            int s = d_csrc[idx];
            float cf = d_dinv[s];
            const float* hp = d_P + (size_t)s*Cc + r*8;
            float4 p0 = *(const float4*)hp;
            float4 p1 = *(const float4*)(hp+4);
            a0.x += cf*p0.x; a0.y += cf*p0.y; a0.z += cf*p0.z; a0.w += cf*p0.w;
            a1.x += cf*p1.x; a1.y += cf*p1.y; a1.z += cf*p1.z; a1.w += cf*p1.w;
        }
    }
    #pragma unroll
    for (int off = 8; off <= 16; off <<= 1) {
        a0.x += __shfl_xor_sync(0xffffffffu, a0.x, off);
        a0.y += __shfl_xor_sync(0xffffffffu, a0.y, off);
        a0.z += __shfl_xor_sync(0xffffffffu, a0.z, off);
        a0.w += __shfl_xor_sync(0xffffffffu, a0.w, off);
        a1.x += __shfl_xor_sync(0xffffffffu, a1.x, off);
        a1.y += __shfl_xor_sync(0xffffffffu, a1.y, off);
        a1.z += __shfl_xor_sync(0xffffffffu, a1.z, off);
        a1.w += __shfl_xor_sync(0xffffffffu, a1.w, off);
    }
    if (g == 0) {
        float dv = d_dinv[v];
        float dvv = dv*dv;
        const float* pp = d_P + (size_t)v*Cc + r*8;
        float4 p0 = *(const float4*)pp;
        float4 p1 = *(const float4*)(pp+4);
        float* Sp = S + (size_t)v*Cc + r*8;
        float4 s0 = *(float4*)Sp;
        float4 s1 = *(float4*)(Sp+4);
        s0.x += dv*a0.x + dvv*p0.x; s0.y += dv*a0.y + dvv*p0.y;
        s0.z += dv*a0.z + dvv*p0.z; s0.w += dv*a0.w + dvv*p0.w;
        s1.x += dv*a1.x + dvv*p1.x; s1.y += dv*a1.y + dvv*p1.y;
        s1.z += dv*a1.z + dvv*p1.z; s1.w += dv*a1.w + dvv*p1.w;
        *(float4*)Sp     = s0;
        *(float4*)(Sp+4) = s1;
    }
}

// ---------------- GAT: single-pass softmax, bf16 feature gather ----------------
__global__ void gat_agg_kernel(float* S, int ko, int nj)
{
    int gw = (blockIdx.x*blockDim.x + threadIdx.x) >> 5;
    if (gw >= Nn) return;
    int lane = threadIdx.x & 31;
    int g = lane >> 3, r = lane & 7;
    int v = gw;
    int beg = d_rowptr[v], end = d_rowptr[v+1];
    float4 t0 = make_float4(0,0,0,0), t1 = make_float4(0,0,0,0);
    for (int j = 0; j < nj; j++) {
        const __nv_bfloat16* hw = d_hwb[j];
        const float* as = d_asrc[j];
        float adv = d_adst[j][v];
        float e0s = as[v] + adv;
        float m = e0s > 0.f ? e0s : 0.2f*e0s;
        float denom = 0.f;
        float4 a0 = make_float4(0,0,0,0), a1 = make_float4(0,0,0,0);
        if (g == 0) {
            denom = 1.f;
            uint4 q = *((const uint4*)(hw + (size_t)v*Cc) + r);
            float2 f0 = __bfloat1622float2(*(__nv_bfloat162*)&q.x);
            float2 f1 = __bfloat1622float2(*(__nv_bfloat162*)&q.y);
            float2 f2 = __bfloat1622float2(*(__nv_bfloat162*)&q.z);
            float2 f3 = __bfloat1622float2(*(__nv_bfloat162*)&q.w);
            a0 = make_float4(f0.x, f0.y, f1.x, f1.y);
            a1 = make_float4(f2.x, f2.y, f3.x, f3.y);
        }
        for (int e0 = beg; e0 < end; e0 += 4) {
            int idx = e0 + g;
            bool valid = idx < end;
            int s = 0;
            if (valid) s = d_csrc[idx];
            float p = 0.f;
            if (valid && r == 0) {
                float tv = as[s] + adv;
                tv = tv > 0.f ? tv : 0.2f*tv;
                p = __expf(tv - m);
            }
            p = __shfl_sync(0xffffffffu, p, lane & 24);
            if (valid) {
                uint4 q = *((const uint4*)(hw + (size_t)s*Cc) + r);
                float2 f0 = __bfloat1622float2(*(__nv_bfloat162*)&q.x);
                float2 f1 = __bfloat1622float2(*(__nv_bfloat162*)&q.y);
                float2 f2 = __bfloat1622float2(*(__nv_bfloat162*)&q.z);
                float2 f3 = __bfloat1622float2(*(__nv_bfloat162*)&q.w);
                a0.x += p*f0.x; a0.y += p*f0.y; a0.z += p*f1.x; a0.w += p*f1.y;
                a1.x += p*f2.x; a1.y += p*f2.y; a1.z += p*f3.x; a1.w += p*f3.y;
                denom += p;
            }
        }
        #pragma unroll
        for (int off = 8; off <= 16; off <<= 1) {
            denom += __shfl_xor_sync(0xffffffffu, denom, off);
            a0.x += __shfl_xor_sync(0xffffffffu, a0.x, off);
            a0.y += __shfl_xor_sync(0xffffffffu, a0.y, off);
            a0.z += __shfl_xor_sync(0xffffffffu, a0.z, off);
            a0.w += __shfl_xor_sync(0xffffffffu, a0.w, off);
            a1.x += __shfl_xor_sync(0xffffffffu, a1.x, off);
            a1.y += __shfl_xor_sync(0xffffffffu, a1.y, off);
            a1.z += __shfl_xor_sync(0xffffffffu, a1.z, off);
            a1.w += __shfl_xor_sync(0xffffffffu, a1.w, off);
        }
        float wcoef = d_w[ko+j][2] / denom;
        t0.x += wcoef*a0.x; t0.y += wcoef*a0.y; t0.z += wcoef*a0.z; t0.w += wcoef*a0.w;
        t1.x += wcoef*a1.x; t1.y += wcoef*a1.y; t1.z += wcoef*a1.z; t1.w += wcoef*a1.w;
    }
    if (g == 0) {
        float* Sp = S + (size_t)v*Cc + r*8;
        float4 s0 = *(float4*)Sp;
        float4 s1 = *(float4*)(Sp+4);
        s0.x += t0.x; s0.y += t0.y; s0.z += t0.z; s0.w += t0.w;
        s1.x += t1.x; s1.y += t1.y; s1.z += t1.z; s1.w += t1.w;
        *(float4*)Sp     = s0;
        *(float4*)(Sp+4) = s1;
    }
}

// ---------------- output ----------------
__global__ void final_kernel(float* out)
{
    int idx = blockIdx.x*blockDim.x + threadIdx.x;
    if (idx >= NC) return;
    out[idx] = 0.25f*(d_s[0][idx] + d_s[1][idx] + d_s[2][idx] + d_s[3][idx]);
}

// ---------------- host orchestration ----------------
extern "C" void kernel_launch(void* const* d_in, const int* in_sizes, int n_in,
                              void* d_out, int out_size)
{
    const float* x       = (const float*)d_in[0];
    const int*   ei      = (const int*)d_in[1];     // int32
    const float* alphas  = (const float*)d_in[2];
    const float* gcn_W   = (const float*)d_in[3];
    const float* gcn_b   = (const float*)d_in[4];
    const float* sage_Wl = (const float*)d_in[5];
    const float* sage_Wr = (const float*)d_in[6];
    const float* sage_b  = (const float*)d_in[7];
    const float* gat_W   = (const float*)d_in[8];
    const float* ga_src  = (const float*)d_in[9];
    const float* ga_dst  = (const float*)d_in[10];
    const float* gat_b   = (const float*)d_in[11];
    float* out = (float*)d_out;
    (void)in_sizes; (void)n_in; (void)out_size;

    float *sbase, *Pp, *aggbase;
    __nv_bfloat16* hwb;
    cudaGetSymbolAddress((void**)&sbase,   d_s);
    cudaGetSymbolAddress((void**)&Pp,      d_P);
    cudaGetSymbolAddress((void**)&hwb,     d_hwb);
    cudaGetSymbolAddress((void**)&aggbase, d_agg);

    const int SMEMSZ = 4096*4 + 2048*4*2;   // 32768 B
    cudaFuncSetAttribute(gemm_kernel, cudaFuncAttributeMaxDynamicSharedMemorySize, SMEMSZ);

    const int NBLK = (Nn + 1023)/1024;   // 49

    zero_indeg_kernel<<<(Nn+511)/512,512>>>();
    prep_w_kernel<<<1,256>>>(alphas, gcn_b, sage_b, gat_b);
    degree_kernel<<<(Ee+255)/256,256>>>(ei);
    scan1_kernel<<<NBLK,1024>>>();
    scan2_kernel<<<1,64>>>(NBLK);
    scan3_kernel<<<NBLK,1024>>>();
    fill_kernel<<<(Ee+255)/256,256>>>(ei);
    sage_agg_kernel<<<6250,256>>>(aggbase, x);

    const int koff[4] = {0,2,5,9};
    for (int step = 0; step < 4; step++) {
        int nj = step + 2;
        int ko = koff[step];
        if (step >= 1)
            sage_agg_kernel<<<6250,256>>>(aggbase + (size_t)step*NC,
                                          sbase + (size_t)(step-1)*NC);

        GArgs ga;
        // job0: combined GCN input P
        {
            GJob& jb = ga.job[0];
            jb.D = Pp; jb.biasStep = -1; jb.gatJ = -1;
            jb.gasrc = nullptr; jb.gadst = nullptr;
            int n = 0;
            jb.t[n++] = GTerm{ x, gcn_W + (size_t)ko*4096, gcn_W + (size_t)(ko+1)*4096,
                               ko, 0, ko+1, 0 };
            for (int j = 2; j < nj; j++)
                jb.t[n++] = GTerm{ sbase + (size_t)(j-2)*NC, gcn_W + (size_t)(ko+j)*4096,
                                   nullptr, ko+j, 0, -1, 0 };
            jb.nt = n;
        }
        // job1: SAGE + identity(diag) + bias -> new state S
        {
            GJob& jb = ga.job[1];
            jb.D = sbase + (size_t)step*NC; jb.biasStep = step; jb.gatJ = -1;
            jb.gasrc = nullptr; jb.gadst = nullptr;
            int n = 0;
            jb.t[n++] = GTerm{ aggbase, sage_Wl + (size_t)ko*4096,
                               sage_Wl + (size_t)(ko+1)*4096, ko, 1, ko+1, 0 };
            jb.t[n++] = GTerm{ x, sage_Wr + (size_t)ko*4096,
                               sage_Wr + (size_t)(ko+1)*4096, ko, 1, ko+1, 1 };
            for (int j = 2; j < nj; j++) {
                jb.t[n++] = GTerm{ aggbase + (size_t)(j-1)*NC,
                                   sage_Wl + (size_t)(ko+j)*4096, nullptr, ko+j, 1, -1, 0 };
                jb.t[n++] = GTerm{ sbase + (size_t)(j-2)*NC,
                                   sage_Wr + (size_t)(ko+j)*4096, nullptr, ko+j, 1, -1, 1 };
            }
            jb.nt = n;
        }
        // jobs 2..: GAT hw_j (bf16 out + fused rowdot)
        for (int j = 0; j < nj; j++) {
            const float* st = (j <= 1) ? x : sbase + (size_t)(j-2)*NC;
            GJob& jb = ga.job[2+j];
            jb.D = (float*)(hwb + (size_t)j*NC); jb.nt = 1;
            jb.biasStep = -1; jb.gatJ = j;
            jb.gasrc = ga_src + (size_t)(ko+j)*Cc;
            jb.gadst = ga_dst + (size_t)(ko+j)*Cc;
            jb.t[0] = GTerm{ st, gat_W + (size_t)(ko+j)*4096, nullptr, -1, 0, -1, 0 };
        }
        gemm_kernel<<<dim3(391, 2+nj), 256, SMEMSZ>>>(ga);

        gcn_agg_kernel<<<6250,256>>>(sbase + (size_t)step*NC);
        gat_agg_kernel<<<6250,256>>>(sbase + (size_t)step*NC, ko, nj);
    }
    final_kernel<<<6250,512>>>(out);
}

// round 13
// speedup vs baseline: 2.6472x; 1.1306x over previous
#include <cuda_runtime.h>
#include <cuda_bf16.h>
#include <math.h>

#define Nn 50000
#define Cc 64
#define Ee 800000
#define NC (Nn*Cc)

// ---------------- device scratch ----------------
__device__ float d_s[4][NC];                // states 2..5 (fp32)
__device__ __nv_bfloat16 d_sb[4][NC];       // bf16 mirrors of states (for SAGE gather)
__device__ __nv_bfloat16 d_xb[NC];          // bf16 mirror of x
__device__ __nv_bfloat16 d_Pb[NC];          // combined GCN input (bf16)
__device__ __nv_bfloat16 d_hwb[5][NC];      // GAT hw_j (bf16)
__device__ float d_agg[4][NC];              // SAGE mean aggregates (fp32)
__device__ float d_asrc[5][Nn];
__device__ float d_adst[5][Nn];
__device__ int   d_indeg[Nn];
__device__ int   d_rowptr[Nn+1];
__device__ int   d_fill[Nn];
__device__ int   d_csrc[Ee];
__device__ float d_dinv[Nn];
__device__ float d_cntinv[Nn];
__device__ float d_w[14][5];
__device__ float d_bias[4][Cc];
__device__ int   d_bsum[64];
__device__ int   d_boff[64];

__device__ __forceinline__ void bf8_to_f(uint4 q, float* f)
{
    float2 f0 = __bfloat1622float2(*(__nv_bfloat162*)&q.x);
    float2 f1 = __bfloat1622float2(*(__nv_bfloat162*)&q.y);
    float2 f2 = __bfloat1622float2(*(__nv_bfloat162*)&q.z);
    float2 f3 = __bfloat1622float2(*(__nv_bfloat162*)&q.w);
    f[0]=f0.x; f[1]=f0.y; f[2]=f1.x; f[3]=f1.y;
    f[4]=f2.x; f[5]=f2.y; f[6]=f3.x; f[7]=f3.y;
}

__global__ void zero_indeg_kernel()
{
    int i = blockIdx.x*blockDim.x + threadIdx.x;
    if (i < Nn) d_indeg[i] = 0;
}

__global__ void cvt_x_kernel(const float* x)
{
    int i = blockIdx.x*blockDim.x + threadIdx.x;
    if (i < NC) d_xb[i] = __float2bfloat16(x[i]);
}

__global__ void prep_w_kernel(const float* alphas, const float* gcn_b,
                              const float* sage_b, const float* gat_b)
{
    int t = threadIdx.x;
    if (t < 14) {
        float v[5]; float m = -1e30f;
        for (int i = 0; i < 5; i++) { v[i] = alphas[t*5+i]; m = fmaxf(m, v[i]); }
        float s = 0.f;
        for (int i = 0; i < 5; i++) { v[i] = expf(v[i]-m); s += v[i]; }
        for (int i = 0; i < 5; i++) d_w[t][i] = v[i]/s;
    }
    __syncthreads();
    int step = t >> 6, c = t & 63;
    const int koff[4] = {0,2,5,9};
    float b = 0.f;
    for (int j = 0; j < step+2; j++) {
        int k = koff[step] + j;
        b += d_w[k][0]*gcn_b[k*Cc+c] + d_w[k][1]*sage_b[k*Cc+c] + d_w[k][2]*gat_b[k*Cc+c];
    }
    d_bias[step][c] = b;
}

// ---------------- CSR construction (edge_index is int32) ----
__global__ void degree_kernel(const int* ei)
{
    int e = blockIdx.x*blockDim.x + threadIdx.x;
    if (e < Ee) {
        int d = ei[Ee + e];
        if ((unsigned)d < (unsigned)Nn) atomicAdd(&d_indeg[d], 1);
    }
}

__global__ void scan1_kernel()
{
    __shared__ int sh[32];
    int b = blockIdx.x, t = threadIdx.x;
    int i = b*1024 + t;
    int v = (i < Nn) ? d_indeg[i] : 0;
    #pragma unroll
    for (int off = 16; off > 0; off >>= 1) v += __shfl_down_sync(0xffffffffu, v, off);
    if ((t & 31) == 0) sh[t >> 5] = v;
    __syncthreads();
    if (t < 32) {
        int s = sh[t];
        #pragma unroll
        for (int off = 16; off > 0; off >>= 1) s += __shfl_down_sync(0xffffffffu, s, off);
        if (t == 0) d_bsum[b] = s;
    }
}

__global__ void scan2_kernel(int nblocks)
{
    __shared__ int sh[64];
    int t = threadIdx.x;
    int v = (t < nblocks) ? d_bsum[t] : 0;
    sh[t] = v;
    __syncthreads();
    #pragma unroll
    for (int off = 1; off < 64; off <<= 1) {
        int xv = (t >= off) ? sh[t-off] : 0;
        __syncthreads();
        sh[t] += xv;
        __syncthreads();
    }
    if (t < nblocks) d_boff[t] = sh[t] - v;
}

__global__ void scan3_kernel()
{
    __shared__ int sh[1024];
    int b = blockIdx.x, t = threadIdx.x;
    int i = b*1024 + t;
    int v = (i < Nn) ? d_indeg[i] : 0;
    sh[t] = v;
    __syncthreads();
    #pragma unroll
    for (int off = 1; off < 1024; off <<= 1) {
        int xv = (t >= off) ? sh[t-off] : 0;
        __syncthreads();
        sh[t] += xv;
        __syncthreads();
    }
    if (i < Nn) {
        int r = d_boff[b] + sh[t] - v;
        d_rowptr[i] = r;
        d_fill[i]   = r;
        d_dinv[i]   = rsqrtf((float)(v+1));
        d_cntinv[i] = 1.0f / (float)(v > 0 ? v : 1);
        if (i == Nn-1) d_rowptr[Nn] = r + v;
    }
}

__global__ void fill_kernel(const int* ei)
{
    int e = blockIdx.x*blockDim.x + threadIdx.x;
    if (e < Ee) {
        int s = ei[e];
        int d = ei[Ee + e];
        if ((unsigned)s < (unsigned)Nn && (unsigned)d < (unsigned)Nn) {
            int pos = atomicAdd(&d_fill[d], 1);
            if ((unsigned)pos < (unsigned)Ee) d_csrc[pos] = s;
        }
    }
}

// ---------------- multi-job GEMM: tensor cores (bf16 3-term split) ----------------
// epilogue: gatJ>=0 -> bf16 out + fused rowdot; gatJ==-2 -> bf16 out; else fp32(+bias)
struct GTerm { const float* A; const float* W; const float* W2; int wk; int wcol; int wk2; int addDiag; };
struct GJob  { float* D; int nt; int biasStep; int gatJ;
               const float* gasrc; const float* gadst; GTerm t[10]; };
struct GArgs { GJob job[7]; };

__device__ __forceinline__ void split2(float2 v, unsigned &hi, unsigned &lo)
{
    __nv_bfloat162 h = __float22bfloat162_rn(v);
    float2 hf = __bfloat1622float2(h);
    __nv_bfloat162 l = __float22bfloat162_rn(make_float2(v.x - hf.x, v.y - hf.y));
    hi = *(unsigned*)&h;
    lo = *(unsigned*)&l;
}

__device__ __forceinline__ void mma16816(float* d, const unsigned* a, const unsigned* b)
{
    asm volatile(
        "mma.sync.aligned.m16n8k16.row.col.f32.bf16.bf16.f32 "
        "{%0,%1,%2,%3},{%4,%5,%6,%7},{%8,%9},{%0,%1,%2,%3};"
        : "+f"(d[0]), "+f"(d[1]), "+f"(d[2]), "+f"(d[3])
        : "r"(a[0]), "r"(a[1]), "r"(a[2]), "r"(a[3]), "r"(b[0]), "r"(b[1]));
}

__global__ void gemm_kernel(GArgs args)
{
    extern __shared__ float sm[];
    float*    Ws = sm;                         // 4096 floats
    unsigned* WH = (unsigned*)(sm + 4096);     // 2048 u32
    unsigned* WL = WH + 2048;                  // 2048 u32
    const GJob& J = args.job[blockIdx.y];
    int tid = threadIdx.x;
    int w = tid >> 5, l = tid & 31;
    int g = l >> 2, t4 = l & 3;
    int row0 = blockIdx.x * 128;
    int r0g = row0 + w*16 + g;
    int r1g = r0g + 8;

    float d[8][4];
    #pragma unroll
    for (int nt = 0; nt < 8; nt++)
        #pragma unroll
        for (int i = 0; i < 4; i++) d[nt][i] = 0.f;

    for (int tm = 0; tm < J.nt; tm++) {
        const float* A  = J.t[tm].A;
        const float* W  = J.t[tm].W;
        const float* W2 = J.t[tm].W2;
        float sc  = (J.t[tm].wk  >= 0) ? d_w[J.t[tm].wk ][J.t[tm].wcol] : 1.0f;
        float sc2 = (J.t[tm].wk2 >= 0) ? d_w[J.t[tm].wk2][J.t[tm].wcol] : 0.0f;
        float dg = 0.f;
        if (J.t[tm].addDiag) {
            dg = d_w[J.t[tm].wk][3];
            if (J.t[tm].wk2 >= 0) dg += d_w[J.t[tm].wk2][3];
        }
        __syncthreads();
        #pragma unroll
        for (int it = 0; it < 4; it++) {
            int idx = tid + it*256;
            float4 v = *(const float4*)(W + idx*4);
            float4 o;
            o.x = sc*v.x; o.y = sc*v.y; o.z = sc*v.z; o.w = sc*v.w;
            if (W2) {
                float4 v2 = *(const float4*)(W2 + idx*4);
                o.x += sc2*v2.x; o.y += sc2*v2.y; o.z += sc2*v2.z; o.w += sc2*v2.w;
            }
            int kk = idx >> 4;
            int dcol = kk - ((idx & 15) * 4);
            if (dg != 0.f && dcol >= 0 && dcol < 4) ((float*)&o)[dcol] += dg;
            *(float4*)(Ws + idx*4) = o;
        }
        __syncthreads();
        #pragma unroll
        for (int it = 0; it < 4; it++) {
            int i = tid + it*256;
            int ks = i >> 8, nt = (i >> 5) & 7, ll = i & 31;
            int tt = ll & 3, gg = ll >> 2;
            int n = nt*8 + gg;
            #pragma unroll
            for (int r = 0; r < 2; r++) {
                int k0 = ks*16 + r*8 + 2*tt;
                float2 f = make_float2(Ws[k0*64 + n], Ws[(k0+1)*64 + n]);
                unsigned hb, lb;
                split2(f, hb, lb);
                int slot = ((ks*8 + nt)*32 + ll)*2 + r;
                WH[slot] = hb;
                WL[slot] = lb;
            }
        }
        __syncthreads();
        #pragma unroll
        for (int ks = 0; ks < 4; ks++) {
            float2 v00 = make_float2(0,0), v01 = v00, v10 = v00, v11 = v00;
            if (r0g < Nn) {
                const float2* Ar = (const float2*)(A + (size_t)r0g*Cc);
                v00 = Ar[ks*8 + t4];
                v01 = Ar[ks*8 + 4 + t4];
            }
            if (r1g < Nn) {
                const float2* Ar = (const float2*)(A + (size_t)r1g*Cc);
                v10 = Ar[ks*8 + t4];
                v11 = Ar[ks*8 + 4 + t4];
            }
            unsigned ah[4], al[4];
            split2(v00, ah[0], al[0]);
            split2(v10, ah[1], al[1]);
            split2(v01, ah[2], al[2]);
            split2(v11, ah[3], al[3]);
            #pragma unroll
            for (int nt = 0; nt < 8; nt++) {
                int slot = ((ks*8 + nt)*32 + l)*2;
                unsigned bh[2], bl[2];
                *(double*)bh = *(const double*)(WH + slot);
                *(double*)bl = *(const double*)(WL + slot);
                mma16816(d[nt], ah, bh);
                mma16816(d[nt], ah, bl);
                mma16816(d[nt], al, bh);
            }
        }
    }

    if (J.gatJ >= 0) {
        // fused rowdot
        float ss0 = 0.f, sd0 = 0.f, ss1 = 0.f, sd1 = 0.f;
        #pragma unroll
        for (int nt = 0; nt < 8; nt++) {
            int c = nt*8 + 2*t4;
            float as0 = J.gasrc[c], as1 = J.gasrc[c+1];
            float ad0 = J.gadst[c], ad1 = J.gadst[c+1];
            ss0 += d[nt][0]*as0 + d[nt][1]*as1;
            sd0 += d[nt][0]*ad0 + d[nt][1]*ad1;
            ss1 += d[nt][2]*as0 + d[nt][3]*as1;
            sd1 += d[nt][2]*ad0 + d[nt][3]*ad1;
        }
        #pragma unroll
        for (int off = 1; off <= 2; off <<= 1) {
            ss0 += __shfl_xor_sync(0xffffffffu, ss0, off);
            sd0 += __shfl_xor_sync(0xffffffffu, sd0, off);
            ss1 += __shfl_xor_sync(0xffffffffu, ss1, off);
            sd1 += __shfl_xor_sync(0xffffffffu, sd1, off);
        }
        if (t4 == 0) {
            if (r0g < Nn) { d_asrc[J.gatJ][r0g] = ss0; d_adst[J.gatJ][r0g] = sd0; }
            if (r1g < Nn) { d_asrc[J.gatJ][r1g] = ss1; d_adst[J.gatJ][r1g] = sd1; }
        }
    }
    if (J.gatJ >= 0 || J.gatJ == -2) {
        __nv_bfloat16* Db = (__nv_bfloat16*)J.D;
        if (r0g < Nn) {
            __nv_bfloat16* Dp = Db + (size_t)r0g*Cc;
            #pragma unroll
            for (int nt = 0; nt < 8; nt++) {
                __nv_bfloat162 hb = __float22bfloat162_rn(make_float2(d[nt][0], d[nt][1]));
                *(unsigned*)(Dp + nt*8 + 2*t4) = *(unsigned*)&hb;
            }
        }
        if (r1g < Nn) {
            __nv_bfloat16* Dp = Db + (size_t)r1g*Cc;
            #pragma unroll
            for (int nt = 0; nt < 8; nt++) {
                __nv_bfloat162 hb = __float22bfloat162_rn(make_float2(d[nt][2], d[nt][3]));
                *(unsigned*)(Dp + nt*8 + 2*t4) = *(unsigned*)&hb;
            }
        }
    } else {
        float2 bs[8];
        #pragma unroll
        for (int nt = 0; nt < 8; nt++) {
            bs[nt] = make_float2(0,0);
            if (J.biasStep >= 0) {
                int col = nt*8 + 2*t4;
                bs[nt].x = d_bias[J.biasStep][col];
                bs[nt].y = d_bias[J.biasStep][col+1];
            }
        }
        if (r0g < Nn) {
            float* Dp = J.D + (size_t)r0g*Cc;
            #pragma unroll
            for (int nt = 0; nt < 8; nt++) {
                int col = nt*8 + 2*t4;
                *(float2*)(Dp + col) = make_float2(d[nt][0]+bs[nt].x, d[nt][1]+bs[nt].y);
            }
        }
        if (r1g < Nn) {
            float* Dp = J.D + (size_t)r1g*Cc;
            #pragma unroll
            for (int nt = 0; nt < 8; nt++) {
                int col = nt*8 + 2*t4;
                *(float2*)(Dp + col) = make_float2(d[nt][2]+bs[nt].x, d[nt][3]+bs[nt].y);
            }
        }
    }
}

// ---------------- SAGE mean aggregate: bf16 gather, 8 edges in flight ----------------
__global__ void sage_agg_kernel(float* agg, const __nv_bfloat16* hb)
{
    int gw = (blockIdx.x*blockDim.x + threadIdx.x) >> 5;
    if (gw >= Nn) return;
    int lane = threadIdx.x & 31;
    int g = lane >> 3, r = lane & 7;
    int v = gw;
    int beg = d_rowptr[v], end = d_rowptr[v+1];
    float acc[8];
    #pragma unroll
    for (int i = 0; i < 8; i++) acc[i] = 0.f;
    for (int e0 = beg; e0 < end; e0 += 8) {
        int iA = e0 + g, iB = e0 + 4 + g;
        bool vA = iA < end, vB = iB < end;
        int sA = vA ? d_csrc[iA] : 0;
        int sB = vB ? d_csrc[iB] : 0;
        if (vA) {
            uint4 q = *((const uint4*)(hb + (size_t)sA*Cc) + r);
            float f[8]; bf8_to_f(q, f);
            #pragma unroll
            for (int i = 0; i < 8; i++) acc[i] += f[i];
        }
        if (vB) {
            uint4 q = *((const uint4*)(hb + (size_t)sB*Cc) + r);
            float f[8]; bf8_to_f(q, f);
            #pragma unroll
            for (int i = 0; i < 8; i++) acc[i] += f[i];
        }
    }
    #pragma unroll
    for (int off = 8; off <= 16; off <<= 1)
        #pragma unroll
        for (int i = 0; i < 8; i++)
            acc[i] += __shfl_xor_sync(0xffffffffu, acc[i], off);
    if (g == 0) {
        float ci = d_cntinv[v];
        float* ap = agg + (size_t)v*Cc + r*8;
        *(float4*)ap     = make_float4(acc[0]*ci, acc[1]*ci, acc[2]*ci, acc[3]*ci);
        *(float4*)(ap+4) = make_float4(acc[4]*ci, acc[5]*ci, acc[6]*ci, acc[7]*ci);
    }
}

// ---------------- fused GCN + GAT edge aggregation ----------------
// warp per node; lanes: g=edge slot (0..3), r=channel slot (0..7)
// scalar gathers (dinv, asrc[j]) spread across r lanes; all rows issued together
template<int NJ>
__global__ void edge_agg_kernel(float* S, __nv_bfloat16* Sb, int ko)
{
    int gw = (blockIdx.x*blockDim.x + threadIdx.x) >> 5;
    if (gw >= Nn) return;
    int lane = threadIdx.x & 31;
    int g = lane >> 3, r = lane & 7;
    int v = gw;
    int beg = d_rowptr[v], end = d_rowptr[v+1];

    float adv = 0.f, mj = 0.f;
    if (r >= 1 && r <= NJ) {
        adv = d_adst[r-1][v];
        float e0s = d_asrc[r-1][v] + adv;
        mj = e0s > 0.f ? e0s : 0.2f*e0s;
    }
    float denomAcc = (g == 0 && r >= 1 && r <= NJ) ? 1.f : 0.f;

    float gacc[8];
    float jacc[NJ][8];
    #pragma unroll
    for (int i = 0; i < 8; i++) gacc[i] = 0.f;
    #pragma unroll
    for (int j = 0; j < NJ; j++) {
        if (g == 0) {
            uint4 q = *((const uint4*)(d_hwb[j] + (size_t)v*Cc) + r);
            float f[8]; bf8_to_f(q, f);
            #pragma unroll
            for (int i = 0; i < 8; i++) jacc[j][i] = f[i];
        } else {
            #pragma unroll
            for (int i = 0; i < 8; i++) jacc[j][i] = 0.f;
        }
    }

    for (int e0 = beg; e0 < end; e0 += 4) {
        int idx = e0 + g;
        bool valid = idx < end;
        int s = valid ? d_csrc[idx] : 0;
        float sval = 0.f;
        if (valid) {
            if (r == 0) sval = d_dinv[s];
            else if (r <= NJ) {
                float a = d_asrc[r-1][s] + adv;
                a = a > 0.f ? a : 0.2f*a;
                sval = __expf(a - mj);
            }
        }
        if (r >= 1 && r <= NJ) denomAcc += sval;
        float cf = __shfl_sync(0xffffffffu, sval, lane & 24);
        if (valid) {
            uint4 q = *((const uint4*)(d_Pb + (size_t)s*Cc) + r);
            float f[8]; bf8_to_f(q, f);
            #pragma unroll
            for (int i = 0; i < 8; i++) gacc[i] += cf*f[i];
        }
        #pragma unroll
        for (int j = 0; j < NJ; j++) {
            float p = __shfl_sync(0xffffffffu, sval, (lane & 24) + 1 + j);
            if (valid) {
                uint4 q = *((const uint4*)(d_hwb[j] + (size_t)s*Cc) + r);
                float f[8]; bf8_to_f(q, f);
                #pragma unroll
                for (int i = 0; i < 8; i++) jacc[j][i] += p*f[i];
            }
        }
    }

    // reduce over g (edge slots)
    #pragma unroll
    for (int off = 8; off <= 16; off <<= 1) {
        denomAcc += __shfl_xor_sync(0xffffffffu, denomAcc, off);
        #pragma unroll
        for (int i = 0; i < 8; i++)
            gacc[i] += __shfl_xor_sync(0xffffffffu, gacc[i], off);
        #pragma unroll
        for (int j = 0; j < NJ; j++)
            #pragma unroll
            for (int i = 0; i < 8; i++)
                jacc[j][i] += __shfl_xor_sync(0xffffffffu, jacc[j][i], off);
    }
    // per-j softmax weights (broadcast denominators; uniform across g after reduction)
    float wcj[NJ];
    #pragma unroll
    for (int j = 0; j < NJ; j++) {
        float dj = __shfl_sync(0xffffffffu, denomAcc, j + 1);
        wcj[j] = d_w[ko+j][2] / dj;
    }

    if (g == 0) {
        float dv = d_dinv[v], dvv = dv*dv;
        uint4 qv = *((const uint4*)(d_Pb + (size_t)v*Cc) + r);
        float fv[8]; bf8_to_f(qv, fv);
        float outv[8];
        #pragma unroll
        for (int i = 0; i < 8; i++) outv[i] = dv*gacc[i] + dvv*fv[i];
        #pragma unroll
        for (int j = 0; j < NJ; j++)
            #pragma unroll
            for (int i = 0; i < 8; i++) outv[i] += wcj[j]*jacc[j][i];

        float* Sp = S + (size_t)v*Cc + r*8;
        float4 s0 = *(float4*)Sp;
        float4 s1 = *(float4*)(Sp+4);
        s0.x += outv[0]; s0.y += outv[1]; s0.z += outv[2]; s0.w += outv[3];
        s1.x += outv[4]; s1.y += outv[5]; s1.z += outv[6]; s1.w += outv[7];
        *(float4*)Sp     = s0;
        *(float4*)(Sp+4) = s1;
        // bf16 mirror of the final state (for next steps' SAGE gather)
        __nv_bfloat162 b0 = __float22bfloat162_rn(make_float2(s0.x, s0.y));
        __nv_bfloat162 b1 = __float22bfloat162_rn(make_float2(s0.z, s0.w));
        __nv_bfloat162 b2 = __float22bfloat162_rn(make_float2(s1.x, s1.y));
        __nv_bfloat162 b3 = __float22bfloat162_rn(make_float2(s1.z, s1.w));
        uint4 q;
        q.x = *(unsigned*)&b0; q.y = *(unsigned*)&b1;
        q.z = *(unsigned*)&b2; q.w = *(unsigned*)&b3;
        *((uint4*)(Sb + (size_t)v*Cc) + r) = q;
    }
}

// ---------------- output ----------------
__global__ void final_kernel(float* out)
{
    int idx = blockIdx.x*blockDim.x + threadIdx.x;
    if (idx >= NC) return;
    out[idx] = 0.25f*(d_s[0][idx] + d_s[1][idx] + d_s[2][idx] + d_s[3][idx]);
}

// ---------------- host orchestration ----------------
extern "C" void kernel_launch(void* const* d_in, const int* in_sizes, int n_in,
                              void* d_out, int out_size)
{
    const float* x       = (const float*)d_in[0];
    const int*   ei      = (const int*)d_in[1];     // int32
    const float* alphas  = (const float*)d_in[2];
    const float* gcn_W   = (const float*)d_in[3];
    const float* gcn_b   = (const float*)d_in[4];
    const float* sage_Wl = (const float*)d_in[5];
    const float* sage_Wr = (const float*)d_in[6];
    const float* sage_b  = (const float*)d_in[7];
    const float* gat_W   = (const float*)d_in[8];
    const float* ga_src  = (const float*)d_in[9];
    const float* ga_dst  = (const float*)d_in[10];
    const float* gat_b   = (const float*)d_in[11];
    float* out = (float*)d_out;
    (void)in_sizes; (void)n_in; (void)out_size;

    float *sbase, *aggbase;
    __nv_bfloat16 *hwb, *Pb, *sb, *xb;
    cudaGetSymbolAddress((void**)&sbase,   d_s);
    cudaGetSymbolAddress((void**)&hwb,     d_hwb);
    cudaGetSymbolAddress((void**)&Pb,      d_Pb);
    cudaGetSymbolAddress((void**)&sb,      d_sb);
    cudaGetSymbolAddress((void**)&xb,      d_xb);
    cudaGetSymbolAddress((void**)&aggbase, d_agg);

    const int SMEMSZ = 4096*4 + 2048*4*2;   // 32768 B
    cudaFuncSetAttribute(gemm_kernel, cudaFuncAttributeMaxDynamicSharedMemorySize, SMEMSZ);

    const int NBLK = (Nn + 1023)/1024;   // 49

    zero_indeg_kernel<<<(Nn+511)/512,512>>>();
    prep_w_kernel<<<1,256>>>(alphas, gcn_b, sage_b, gat_b);
    cvt_x_kernel<<<(NC+511)/512,512>>>(x);
    degree_kernel<<<(Ee+255)/256,256>>>(ei);
    scan1_kernel<<<NBLK,1024>>>();
    scan2_kernel<<<1,64>>>(NBLK);
    scan3_kernel<<<NBLK,1024>>>();
    fill_kernel<<<(Ee+255)/256,256>>>(ei);
    sage_agg_kernel<<<6250,256>>>(aggbase, xb);

    const int koff[4] = {0,2,5,9};
    for (int step = 0; step < 4; step++) {
        int nj = step + 2;
        int ko = koff[step];
        if (step >= 1)
            sage_agg_kernel<<<6250,256>>>(aggbase + (size_t)step*NC,
                                          sb + (size_t)(step-1)*NC);

        GArgs ga;
        // job0: combined GCN input P (bf16 out)
        {
            GJob& jb = ga.job[0];
            jb.D = (float*)Pb; jb.biasStep = -1; jb.gatJ = -2;
            jb.gasrc = nullptr; jb.gadst = nullptr;
            int n = 0;
            jb.t[n++] = GTerm{ x, gcn_W + (size_t)ko*4096, gcn_W + (size_t)(ko+1)*4096,
                               ko, 0, ko+1, 0 };
            for (int j = 2; j < nj; j++)
                jb.t[n++] = GTerm{ sbase + (size_t)(j-2)*NC, gcn_W + (size_t)(ko+j)*4096,
                                   nullptr, ko+j, 0, -1, 0 };
            jb.nt = n;
        }
        // job1: SAGE + identity(diag) + bias -> new state S (fp32)
        {
            GJob& jb = ga.job[1];
            jb.D = sbase + (size_t)step*NC; jb.biasStep = step; jb.gatJ = -1;
            jb.gasrc = nullptr; jb.gadst = nullptr;
            int n = 0;
            jb.t[n++] = GTerm{ aggbase, sage_Wl + (size_t)ko*4096,
                               sage_Wl + (size_t)(ko+1)*4096, ko, 1, ko+1, 0 };
            jb.t[n++] = GTerm{ x, sage_Wr + (size_t)ko*4096,
                               sage_Wr + (size_t)(ko+1)*4096, ko, 1, ko+1, 1 };
            for (int j = 2; j < nj; j++) {
                jb.t[n++] = GTerm{ aggbase + (size_t)(j-1)*NC,
                                   sage_Wl + (size_t)(ko+j)*4096, nullptr, ko+j, 1, -1, 0 };
                jb.t[n++] = GTerm{ sbase + (size_t)(j-2)*NC,
                                   sage_Wr + (size_t)(ko+j)*4096, nullptr, ko+j, 1, -1, 1 };
            }
            jb.nt = n;
        }
        // jobs 2..: GAT hw_j (bf16 out + fused rowdot)
        for (int j = 0; j < nj; j++) {
            const float* st = (j <= 1) ? x : sbase + (size_t)(j-2)*NC;
            GJob& jb = ga.job[2+j];
            jb.D = (float*)(hwb + (size_t)j*NC); jb.nt = 1;
            jb.biasStep = -1; jb.gatJ = j;
            jb.gasrc = ga_src + (size_t)(ko+j)*Cc;
            jb.gadst = ga_dst + (size_t)(ko+j)*Cc;
            jb.t[0] = GTerm{ st, gat_W + (size_t)(ko+j)*4096, nullptr, -1, 0, -1, 0 };
        }
        gemm_kernel<<<dim3(391, 2+nj), 256, SMEMSZ>>>(ga);

        float* Sp = sbase + (size_t)step*NC;
        __nv_bfloat16* Sbp = sb + (size_t)step*NC;
        switch (nj) {
            case 2: edge_agg_kernel<2><<<6250,256>>>(Sp, Sbp, ko); break;
            case 3: edge_agg_kernel<3><<<6250,256>>>(Sp, Sbp, ko); break;
            case 4: edge_agg_kernel<4><<<6250,256>>>(Sp, Sbp, ko); break;
            default: edge_agg_kernel<5><<<6250,256>>>(Sp, Sbp, ko); break;
        }
    }
    final_kernel<<<6250,512>>>(out);
}